// round 5
// baseline (speedup 1.0000x reference)
#include <cstdint>
#include <cuda_runtime.h>
#include <cuda_bf16.h>
#include <mma.h>

using namespace nvcuda;
typedef __nv_bfloat16 bf;

#define Bn 2
#define Dm 256
#define Cc 64
#define Tt 1024
#define Hh 8
#define Ff 32
#define CT 65536
#define E3 768
#define EPS 1e-5f
#define SCALE 0.1767766952966369f
#define TC 128

// ---------------- scratch ----------------
__device__ __align__(128) bf g_xbf[(size_t)Bn * Dm * CT];            // 67 MB
__device__ __align__(128) bf g_weff[(size_t)Bn * E3 * Dm];
__device__ float g_mu[Bn * Dm];
__device__ float g_rstd[Bn * Dm];
__device__ float g_bias[Bn * E3];
__device__ __align__(128) bf g_wout[Dm * Dm];
__device__ __align__(128) bf g_qt[(size_t)Bn * Cc * Dm * Tt];        // [bc][e][t] 67 MB
__device__ __align__(128) bf g_ctx[(size_t)Bn * Cc * Hh * Ff * Ff];  // [bc][h][fv][fk]
__device__ __align__(128) bf g_mcat[(size_t)Bn * Cc * Dm * Dm];      // [bc][e][col] 16.8 MB

// ---------------- cp.async ----------------
__device__ __forceinline__ void cp16(void* smem, const void* gmem) {
    unsigned s = (unsigned)__cvta_generic_to_shared(smem);
    asm volatile("cp.async.cg.shared.global [%0], [%1], 16;\n" :: "r"(s), "l"(gmem));
}
#define CP_COMMIT() asm volatile("cp.async.commit_group;\n")
#define CP_WAIT1()  asm volatile("cp.async.wait_group 1;\n")
#define CP_WAIT0()  asm volatile("cp.async.wait_group 0;\n")

// ---------------- K1: stats + convert x to bf16 ----------------
__global__ __launch_bounds__(256) void stats_cvt(const float* __restrict__ x) {
    size_t base = (size_t)blockIdx.x * CT;
    const float4* p = (const float4*)(x + base);
    bf* ob = g_xbf + base;
    float s = 0.f, ss = 0.f;
    for (int i = threadIdx.x; i < CT / 4; i += 256) {
        float4 v = p[i];
        s += v.x + v.y + v.z + v.w;
        ss += v.x * v.x + v.y * v.y + v.z * v.z + v.w * v.w;
        union { uint2 u; __nv_bfloat162 h[2]; } pk;
        pk.h[0] = __floats2bfloat162_rn(v.x, v.y);
        pk.h[1] = __floats2bfloat162_rn(v.z, v.w);
        *(uint2*)(ob + (size_t)i * 4) = pk.u;
    }
    __shared__ float rs[8], rss[8];
    for (int off = 16; off; off >>= 1) {
        s  += __shfl_down_sync(~0u, s, off);
        ss += __shfl_down_sync(~0u, ss, off);
    }
    int wid = threadIdx.x >> 5, lane = threadIdx.x & 31;
    if (lane == 0) { rs[wid] = s; rss[wid] = ss; }
    __syncthreads();
    if (threadIdx.x == 0) {
        float S = 0.f, SS = 0.f;
        for (int i = 0; i < 8; i++) { S += rs[i]; SS += rss[i]; }
        float mu = S / (float)CT;
        float var = SS / (float)CT - mu * mu;
        g_mu[blockIdx.x] = mu;
        g_rstd[blockIdx.x] = rsqrtf(var + EPS);
    }
}

// ---------------- K2: fold instance norm into weights ----------------
__global__ __launch_bounds__(256) void prep_weights(const float* __restrict__ in_w,
                                                    const float* __restrict__ in_b) {
    int be = blockIdx.x;
    int b = be / E3, e = be % E3;
    int d = threadIdx.x;
    float w = in_w[e * Dm + d];
    float r = g_rstd[b * Dm + d];
    float m = g_mu[b * Dm + d];
    float we = w * r;
    g_weff[(size_t)be * Dm + d] = __float2bfloat16(we);
    __shared__ float red[256];
    red[d] = we * m;
    __syncthreads();
    for (int s = 128; s > 0; s >>= 1) {
        if (d < s) red[d] += red[d + s];
        __syncthreads();
    }
    if (d == 0) g_bias[be] = in_b[e] - red[0];
}

__global__ __launch_bounds__(256) void conv_outw(const float* __restrict__ out_w) {
    int i = blockIdx.x * 256 + threadIdx.x;
    g_wout[i] = __float2bfloat16(out_w[i]);
}

// ---------------- K3: fused qkv GEMM + attention stats/ctx + q-softmax ----------------
// One block per (b,c). Streams x in t-chunks; per chunk computes qkv via wmma GEMM,
// immediately consumes k (unnormalized exp + running S), v (ctx wmma accumulation in
// persistent registers), and writes softmaxed q~ to gmem. End: normalized ctx out.
//
// Dynamic smem layout (bytes):
//  A_s    [2][128][72] bf16    @ 0        36864
//  X_s    [256][136]  bf16     @ 36864    69632
//  KB     [128][136]  bf16     @ 106496   34816
//  VB     [128][136]  bf16     @ 141312   34816
//  ST     [64][144]   f32      @ 176128   36864   (also ctx stage [8][32][36] f32)
//  S_s    [256]       f32      @ 212992   1024
//  bias_s [768]       f32      @ 214016   3072
//  total 217088
#define SM_A   0
#define SM_X   36864
#define SM_KB  106496
#define SM_VB  141312
#define SM_ST  176128
#define SM_S   212992
#define SM_BI  214016
#define SM_TOTAL 217088

__global__ __launch_bounds__(256, 1) void fused_qkv_attn() {
    extern __shared__ char smem[];
    bf* A_s   = (bf*)(smem + SM_A);     // [2][128][72]
    bf* X_s   = (bf*)(smem + SM_X);     // [256][136]
    bf* KB    = (bf*)(smem + SM_KB);    // [128][136]
    bf* VB    = (bf*)(smem + SM_VB);    // [128][136]
    float* ST = (float*)(smem + SM_ST); // [64][144]
    float* S_s = (float*)(smem + SM_S);
    float* bias_s = (float*)(smem + SM_BI);

    const int bc = blockIdx.x;
    const int b = bc >> 6, c = bc & 63;
    const int tid = threadIdx.x;
    const int w = tid >> 5, lane = tid & 31;
    const int wm = w >> 2, wn = w & 3;

    const bf* Wb = g_weff + (size_t)b * E3 * Dm;

    for (int i = tid; i < E3; i += 256) bias_s[i] = g_bias[b * E3 + i];
    if (tid < 256) S_s[tid] = 0.f;

    // persistent ctx accumulators: warp w owns (head hl=w>>1, fk-half i2=w&1), j in {0,1}
    wmma::fragment<wmma::accumulator, 16, 16, 16, float> cacc0[2], cacc1[2];
    wmma::fill_fragment(cacc0[0], 0.f); wmma::fill_fragment(cacc0[1], 0.f);
    wmma::fill_fragment(cacc1[0], 0.f); wmma::fill_fragment(cacc1[1], 0.f);

    wmma::fragment<wmma::accumulator, 16, 16, 16, float> acc[4][2];

    __syncthreads();

    int tc = 0;   // captured by lambdas
    // -------- GEMM of one 128-row e-tile over full K=256 --------
    auto gemm_tile = [&](int ebase) {
        #pragma unroll
        for (int i = 0; i < 4; i++)
            #pragma unroll
            for (int j = 0; j < 2; j++) wmma::fill_fragment(acc[i][j], 0.f);
        auto loadA = [&](int s, int k0) {
            #pragma unroll
            for (int it = 0; it < 4; it++) {
                int idx = tid + it * 256;
                int r = idx >> 3, c8 = (idx & 7) * 8;
                cp16(A_s + (s * 128 + r) * 72 + c8,
                     Wb + (size_t)(ebase + r) * Dm + k0 + c8);
            }
        };
        loadA(0, 0); CP_COMMIT();
        #pragma unroll
        for (int ks = 0; ks < 4; ks++) {
            int cur = ks & 1;
            if (ks < 3) { loadA(cur ^ 1, (ks + 1) * 64); CP_COMMIT(); CP_WAIT1(); }
            else CP_WAIT0();
            __syncthreads();
            #pragma unroll
            for (int kk = 0; kk < 64; kk += 16) {
                int kg = ks * 64 + kk;
                wmma::fragment<wmma::matrix_a, 16, 16, 16, bf, wmma::row_major> af[4];
                wmma::fragment<wmma::matrix_b, 16, 16, 16, bf, wmma::row_major> bfr[2];
                #pragma unroll
                for (int i = 0; i < 4; i++)
                    wmma::load_matrix_sync(af[i], A_s + (cur * 128 + wm * 64 + i * 16) * 72 + kk, 72);
                #pragma unroll
                for (int j = 0; j < 2; j++)
                    wmma::load_matrix_sync(bfr[j], X_s + kg * 136 + wn * 32 + j * 16, 136);
                #pragma unroll
                for (int i = 0; i < 4; i++)
                    #pragma unroll
                    for (int j = 0; j < 2; j++)
                        wmma::mma_sync(acc[i][j], af[i], bfr[j], acc[i][j]);
            }
            __syncthreads();
        }
    };
    auto epi_store = [&](int g) {
        if (wm == g) {
            #pragma unroll
            for (int i = 0; i < 4; i++)
                #pragma unroll
                for (int j = 0; j < 2; j++)
                    wmma::store_matrix_sync(ST + (i * 16) * 144 + wn * 32 + j * 16,
                                            acc[i][j], 144, wmma::mem_row_major);
        }
        __syncthreads();
    };

    auto do_q = [&](int ebase) {
        gemm_tile(ebase);
        #pragma unroll
        for (int g = 0; g < 2; g++) {
            epi_store(g);
            {   // column softmax over each 32-row head block
                int col = tid & 127, hb = tid >> 7;
                int rbase = hb * 32;
                int eb = ebase + g * 64 + rbase;
                float vbuf[32];
                float m = -1e30f;
                #pragma unroll
                for (int rr = 0; rr < 32; rr++) {
                    float vv = ST[(rbase + rr) * 144 + col] + bias_s[eb + rr];
                    vbuf[rr] = vv; m = fmaxf(m, vv);
                }
                float s = 0.f;
                #pragma unroll
                for (int rr = 0; rr < 32; rr++) { vbuf[rr] = __expf(vbuf[rr] - m); s += vbuf[rr]; }
                float inv = SCALE / s;
                #pragma unroll
                for (int rr = 0; rr < 32; rr++)
                    KB[(g * 64 + rbase + rr) * 136 + col] = __float2bfloat16(vbuf[rr] * inv);
            }
            __syncthreads();
        }
        // copy q~ tile to gmem
        #pragma unroll
        for (int it = 0; it < 8; it++) {
            int idx = tid + it * 256;
            int r = idx >> 4, c8 = (idx & 15) * 8;
            *(uint4*)(g_qt + ((size_t)bc * Dm + ebase + r) * Tt + tc + c8) =
                *(uint4*)(KB + r * 136 + c8);
        }
    };

    auto do_k = [&](int ebase, int klocal) {
        gemm_tile(ebase);
        #pragma unroll
        for (int g = 0; g < 2; g++) {
            epi_store(g);
            {
                int r = tid >> 2, strip = tid & 3;
                int rowL = g * 64 + r;
                float bsv = bias_s[ebase + rowL];
                float part = 0.f;
                #pragma unroll
                for (int cc2 = 0; cc2 < 32; cc2++) {
                    int col = strip * 32 + cc2;
                    float ee = __expf(ST[r * 144 + col] + bsv);
                    KB[rowL * 136 + col] = __float2bfloat16(ee);
                    part += ee;
                }
                part += __shfl_xor_sync(~0u, part, 1);
                part += __shfl_xor_sync(~0u, part, 2);
                if (strip == 0) S_s[klocal + rowL] += part;
            }
            __syncthreads();
        }
    };

    auto do_v = [&](int ebase) {
        gemm_tile(ebase);
        #pragma unroll
        for (int g = 0; g < 2; g++) {
            epi_store(g);
            {
                int r = tid >> 2, strip = tid & 3;
                int rowL = g * 64 + r;
                float bsv = bias_s[ebase + rowL];
                #pragma unroll
                for (int cc2 = 0; cc2 < 32; cc2++) {
                    int col = strip * 32 + cc2;
                    VB[rowL * 136 + col] =
                        __float2bfloat16((ST[r * 144 + col] + bsv) * (1.0f / 1024.0f));
                }
            }
            __syncthreads();
        }
    };

    auto ctx_pass = [&](wmma::fragment<wmma::accumulator, 16, 16, 16, float>* cc) {
        int hl = w >> 1, i2 = w & 1;
        #pragma unroll
        for (int t16 = 0; t16 < TC; t16 += 16) {
            wmma::fragment<wmma::matrix_a, 16, 16, 16, bf, wmma::row_major> af;
            wmma::load_matrix_sync(af, KB + (hl * 32 + i2 * 16) * 136 + t16, 136);
            #pragma unroll
            for (int j = 0; j < 2; j++) {
                wmma::fragment<wmma::matrix_b, 16, 16, 16, bf, wmma::col_major> bfr;
                wmma::load_matrix_sync(bfr, VB + (hl * 32 + j * 16) * 136 + t16, 136);
                wmma::mma_sync(cc[j], af, bfr, cc[j]);
            }
        }
    };

    for (tc = 0; tc < Tt; tc += TC) {
        // load x chunk [256 d][128 t]
        #pragma unroll
        for (int it = 0; it < 16; it++) {
            int idx = tid + it * 256;
            int r = idx >> 4, c8 = (idx & 15) * 8;
            cp16(X_s + r * 136 + c8,
                 g_xbf + ((size_t)(b * Dm + r) * Cc + c) * Tt + tc + c8);
        }
        CP_COMMIT();
        do_q(0);
        do_q(128);
        do_k(256, 0);     // heads 0-3 k
        do_v(512);        // heads 0-3 v
        ctx_pass(cacc0);
        do_k(384, 128);   // heads 4-7 k
        do_v(640);        // heads 4-7 v
        ctx_pass(cacc1);
    }

    __syncthreads();
    // store ctx partial tiles: ST as [8 heads][32 fk][36]
    {
        int hl = w >> 1, i2 = w & 1;
        #pragma unroll
        for (int j = 0; j < 2; j++) {
            wmma::store_matrix_sync(ST + (hl * 32 + i2 * 16) * 36 + j * 16,
                                    cacc0[j], 36, wmma::mem_row_major);
            wmma::store_matrix_sync(ST + ((4 + hl) * 32 + i2 * 16) * 36 + j * 16,
                                    cacc1[j], 36, wmma::mem_row_major);
        }
    }
    __syncthreads();
    // normalize by S and write transposed [bc][h][fv][fk]
    for (int fk = 0; fk < 32; fk++) {
        float val = ST[(w * 32 + fk) * 36 + lane] / S_s[w * 32 + fk];
        g_ctx[(((size_t)bc * Hh + w) * Ff + lane) * Ff + fk] = __float2bfloat16(val);
    }
}

// ---------------- K4: Mcat[bc] = W_out x blockdiag(ctx^T) ----------------
__global__ __launch_bounds__(256) void mcat_kernel() {
    int bc = blockIdx.x;
    __shared__ bf ctxs[8192];   // [h][fv][fk]
    int tid = threadIdx.x;
    for (int i = tid; i < 8192; i += 256) ctxs[i] = g_ctx[(size_t)bc * 8192 + i];
    __syncthreads();
    int e = tid;
    const bf* wrow = g_wout + e * Dm;
    #pragma unroll 1
    for (int h = 0; h < 8; h++) {
        float wv[32];
        #pragma unroll
        for (int fv = 0; fv < 32; fv++) wv[fv] = __bfloat162float(wrow[h * 32 + fv]);
        float o[32];
        #pragma unroll
        for (int fk = 0; fk < 32; fk++) o[fk] = 0.f;
        #pragma unroll
        for (int fv = 0; fv < 32; fv++) {
            float wf = wv[fv];
            const bf* cr = ctxs + h * 1024 + fv * 32;
            #pragma unroll
            for (int fk = 0; fk < 32; fk++) o[fk] += wf * __bfloat162float(cr[fk]);
        }
        __align__(16) bf ob[32];
        #pragma unroll
        for (int fk = 0; fk < 32; fk++) ob[fk] = __float2bfloat16(o[fk]);
        uint4* dst = (uint4*)(g_mcat + ((size_t)bc * Dm + e) * Dm + h * 32);
        const uint4* src = (const uint4*)ob;
        #pragma unroll
        for (int q2 = 0; q2 < 4; q2++) dst[q2] = src[q2];
    }
}

// ---------------- K5: out = Mcat[bc] @ q~ + out_b + x ----------------
__global__ __launch_bounds__(256) void final_gemm(const float* __restrict__ x,
                                                  const float* __restrict__ out_b,
                                                  float* __restrict__ out) {
    const int bx = blockIdx.x;   // t tile (8 of 128)
    const int by = blockIdx.y;   // e half (2 of 128)
    const int bc = blockIdx.z;   // 128
    const int b = bc >> 6, c = bc & 63;

    __shared__ __align__(16) char smem_raw[2 * 128 * 40 * 2 + 2 * 32 * 136 * 2];
    bf (*A_s)[128][40]  = (bf(*)[128][40])smem_raw;
    bf (*B_s)[32][136]  = (bf(*)[32][136])(smem_raw + 2 * 128 * 40 * 2);
    float (*stage)[132] = (float(*)[132])smem_raw;

    const int tid = threadIdx.x;
    const int w = tid >> 5;
    const int wm = w >> 2, wn = w & 3;

    const bf* Aptr = g_mcat + (size_t)bc * Dm * Dm + (size_t)by * 128 * Dm;
    const bf* Bptr = g_qt + (size_t)bc * Dm * Tt + bx * 128;

    wmma::fragment<wmma::accumulator, 16, 16, 16, float> acc[4][2];
    #pragma unroll
    for (int i = 0; i < 4; i++)
        #pragma unroll
        for (int j = 0; j < 2; j++) wmma::fill_fragment(acc[i][j], 0.0f);

    auto loadA = [&](int s, int k0) {
        #pragma unroll
        for (int it = 0; it < 2; it++) {
            int idx = tid + it * 256;
            int r = idx >> 2, c8 = (idx & 3) * 8;
            cp16(&A_s[s][r][c8], Aptr + (size_t)r * Dm + k0 + c8);
        }
    };
    auto loadB = [&](int s, int k0) {
        #pragma unroll
        for (int it = 0; it < 2; it++) {
            int idx = tid + it * 256;
            int r = idx >> 4, c8 = (idx & 15) * 8;
            cp16(&B_s[s][r][c8], Bptr + (size_t)(k0 + r) * Tt + c8);
        }
    };

    loadA(0, 0); loadB(0, 0); CP_COMMIT();

    for (int ks = 0; ks < 8; ks++) {
        int cur = ks & 1;
        if (ks < 7) {
            loadA(cur ^ 1, (ks + 1) * 32);
            loadB(cur ^ 1, (ks + 1) * 32);
            CP_COMMIT();
            CP_WAIT1();
        } else {
            CP_WAIT0();
        }
        __syncthreads();
        #pragma unroll
        for (int kk = 0; kk < 32; kk += 16) {
            wmma::fragment<wmma::matrix_a, 16, 16, 16, bf, wmma::row_major> af[4];
            wmma::fragment<wmma::matrix_b, 16, 16, 16, bf, wmma::row_major> bfr[2];
            #pragma unroll
            for (int i = 0; i < 4; i++)
                wmma::load_matrix_sync(af[i], &A_s[cur][wm * 64 + i * 16][kk], 40);
            #pragma unroll
            for (int j = 0; j < 2; j++)
                wmma::load_matrix_sync(bfr[j], &B_s[cur][kk][wn * 32 + j * 16], 136);
            #pragma unroll
            for (int i = 0; i < 4; i++)
                #pragma unroll
                for (int j = 0; j < 2; j++)
                    wmma::mma_sync(acc[i][j], af[i], bfr[j], acc[i][j]);
        }
        __syncthreads();
    }

    #pragma unroll
    for (int ch = 0; ch < 2; ch++) {
        if (wm == ch) {
            #pragma unroll
            for (int i = 0; i < 4; i++)
                #pragma unroll
                for (int j = 0; j < 2; j++)
                    wmma::store_matrix_sync(&stage[i * 16][wn * 32 + j * 16],
                                            acc[i][j], 132, wmma::mem_row_major);
        }
        __syncthreads();
        for (int idx = tid; idx < 64 * 128; idx += 256) {
            int r = idx >> 7, cc = idx & 127;
            int e = by * 128 + ch * 64 + r;
            size_t gi = ((size_t)(b * Dm + e) * Cc + c) * Tt + bx * 128 + cc;
            out[gi] = stage[r][cc] + out_b[e] + x[gi];
        }
        __syncthreads();
    }
}

// ---------------- launch ----------------
extern "C" void kernel_launch(void* const* d_in, const int* in_sizes, int n_in,
                              void* d_out, int out_size) {
    const float* x     = (const float*)d_in[0];
    const float* in_w  = (const float*)d_in[1];
    const float* in_b  = (const float*)d_in[2];
    const float* out_w = (const float*)d_in[3];
    const float* out_b = (const float*)d_in[4];
    float* out = (float*)d_out;

    static bool attr_set = false;
    if (!attr_set) {
        cudaFuncSetAttribute(fused_qkv_attn,
                             cudaFuncAttributeMaxDynamicSharedMemorySize, SM_TOTAL);
        attr_set = true;
    }

    stats_cvt<<<Bn * Dm, 256>>>(x);
    prep_weights<<<Bn * E3, 256>>>(in_w, in_b);
    conv_outw<<<Dm * Dm / 256, 256>>>(out_w);
    fused_qkv_attn<<<Bn * Cc, 256, SM_TOTAL>>>();
    mcat_kernel<<<Bn * Cc, 256>>>();
    final_gemm<<<dim3(Tt / 128, 2, Bn * Cc), 256>>>(x, out_b, out);
}

// round 6
// speedup vs baseline: 1.2628x; 1.2628x over previous
#include <cstdint>
#include <cuda_runtime.h>
#include <cuda_bf16.h>
#include <mma.h>

using namespace nvcuda;
typedef __nv_bfloat16 bf;

#define Bn 2
#define Dm 256
#define Cc 64
#define Tt 1024
#define Hh 8
#define Ff 32
#define CT 65536
#define E3 768
#define EPS 1e-5f
#define SCALE 0.1767766952966369f

// ---------------- scratch ----------------
__device__ __align__(128) bf g_xbf[(size_t)Bn * Dm * CT];            // 67 MB
__device__ __align__(128) bf g_qkv[(size_t)Bn * E3 * CT];            // 201 MB (q part = q~)
__device__ __align__(128) bf g_weff[(size_t)Bn * E3 * Dm];
__device__ float g_mu[Bn * Dm];
__device__ float g_rstd[Bn * Dm];
__device__ float g_bias[Bn * E3];
__device__ __align__(128) bf g_wout[Dm * Dm];
__device__ __align__(128) bf g_ctx[(size_t)Bn * Cc * Hh * Ff * Ff];  // [bc][h][fv][fk]
__device__ __align__(128) bf g_mcat[(size_t)Bn * Cc * Dm * Dm];      // 16.8 MB

// ---------------- cp.async ----------------
__device__ __forceinline__ void cp16(void* smem, const void* gmem) {
    unsigned s = (unsigned)__cvta_generic_to_shared(smem);
    asm volatile("cp.async.cg.shared.global [%0], [%1], 16;\n" :: "r"(s), "l"(gmem));
}
#define CP_COMMIT() asm volatile("cp.async.commit_group;\n")
#define CP_WAIT1()  asm volatile("cp.async.wait_group 1;\n")
#define CP_WAIT0()  asm volatile("cp.async.wait_group 0;\n")

// ---------------- K1: stats + convert x to bf16 ----------------
__global__ __launch_bounds__(256) void stats_cvt(const float* __restrict__ x) {
    size_t base = (size_t)blockIdx.x * CT;
    const float4* p = (const float4*)(x + base);
    bf* ob = g_xbf + base;
    float s = 0.f, ss = 0.f;
    for (int i = threadIdx.x; i < CT / 4; i += 256) {
        float4 v = p[i];
        s += v.x + v.y + v.z + v.w;
        ss += v.x * v.x + v.y * v.y + v.z * v.z + v.w * v.w;
        union { uint2 u; __nv_bfloat162 h[2]; } pk;
        pk.h[0] = __floats2bfloat162_rn(v.x, v.y);
        pk.h[1] = __floats2bfloat162_rn(v.z, v.w);
        *(uint2*)(ob + (size_t)i * 4) = pk.u;
    }
    __shared__ float rs[8], rss[8];
    for (int off = 16; off; off >>= 1) {
        s  += __shfl_down_sync(~0u, s, off);
        ss += __shfl_down_sync(~0u, ss, off);
    }
    int wid = threadIdx.x >> 5, lane = threadIdx.x & 31;
    if (lane == 0) { rs[wid] = s; rss[wid] = ss; }
    __syncthreads();
    if (threadIdx.x == 0) {
        float S = 0.f, SS = 0.f;
        for (int i = 0; i < 8; i++) { S += rs[i]; SS += rss[i]; }
        float mu = S / (float)CT;
        float var = SS / (float)CT - mu * mu;
        g_mu[blockIdx.x] = mu;
        g_rstd[blockIdx.x] = rsqrtf(var + EPS);
    }
}

// ---------------- K2: fold instance norm into weights ----------------
__global__ __launch_bounds__(256) void prep_weights(const float* __restrict__ in_w,
                                                    const float* __restrict__ in_b) {
    int be = blockIdx.x;
    int b = be / E3, e = be % E3;
    int d = threadIdx.x;
    float w = in_w[e * Dm + d];
    float r = g_rstd[b * Dm + d];
    float m = g_mu[b * Dm + d];
    float we = w * r;
    g_weff[(size_t)be * Dm + d] = __float2bfloat16(we);
    __shared__ float red[256];
    red[d] = we * m;
    __syncthreads();
    for (int s = 128; s > 0; s >>= 1) {
        if (d < s) red[d] += red[d + s];
        __syncthreads();
    }
    if (d == 0) g_bias[be] = in_b[e] - red[0];
}

__global__ __launch_bounds__(256) void conv_outw(const float* __restrict__ out_w) {
    int i = blockIdx.x * 256 + threadIdx.x;
    g_wout[i] = __float2bfloat16(out_w[i]);
}

// ---------------- K3: qkv GEMM, 4 warps, 64x64 warp tiles, fused q-softmax ----------------
// block tile 128(M e) x 128(N t), BK=32, double buffered cp.async. 128 threads.
__global__ __launch_bounds__(128) void qkv_gemm() {
    const int bx = blockIdx.x;   // t tile (512)
    const int by = blockIdx.y;   // e tile (6); by<2 => q
    const int b  = blockIdx.z;

    __shared__ __align__(16) char smem_raw[2 * 128 * 40 * 2 + 2 * 32 * 136 * 2];
    bf (*A_s)[128][40]  = (bf(*)[128][40])smem_raw;
    bf (*B_s)[32][136]  = (bf(*)[32][136])(smem_raw + 2 * 128 * 40 * 2);
    float (*stage)[132] = (float(*)[132])smem_raw;   // 64x132 f32 fits (33.8KB)
    __shared__ float biasT[128];

    const int tid = threadIdx.x;
    const int w = tid >> 5;
    const int wm = w >> 1, wn = w & 1;   // 2x2 warps, 64x64 tiles

    if (tid < 128) biasT[tid] = g_bias[b * E3 + by * 128 + tid];

    const bf* Aptr = g_weff + (size_t)(b * E3 + by * 128) * Dm;
    const bf* Bptr = g_xbf + (size_t)b * Dm * CT + (size_t)bx * 128;

    wmma::fragment<wmma::accumulator, 16, 16, 16, float> acc[4][4];
    #pragma unroll
    for (int i = 0; i < 4; i++)
        #pragma unroll
        for (int j = 0; j < 4; j++) wmma::fill_fragment(acc[i][j], 0.0f);

    auto loadA = [&](int s, int k0) {
        #pragma unroll
        for (int it = 0; it < 4; it++) {
            int idx = tid + it * 128;
            int r = idx >> 2, c8 = (idx & 3) * 8;
            cp16(&A_s[s][r][c8], Aptr + (size_t)r * Dm + k0 + c8);
        }
    };
    auto loadB = [&](int s, int k0) {
        #pragma unroll
        for (int it = 0; it < 4; it++) {
            int idx = tid + it * 128;
            int r = idx >> 4, c8 = (idx & 15) * 8;
            cp16(&B_s[s][r][c8], Bptr + (size_t)(k0 + r) * CT + c8);
        }
    };

    loadA(0, 0); loadB(0, 0); CP_COMMIT();

    for (int ks = 0; ks < 8; ks++) {
        int cur = ks & 1;
        if (ks < 7) {
            loadA(cur ^ 1, (ks + 1) * 32);
            loadB(cur ^ 1, (ks + 1) * 32);
            CP_COMMIT();
            CP_WAIT1();
        } else {
            CP_WAIT0();
        }
        __syncthreads();
        #pragma unroll
        for (int kk = 0; kk < 32; kk += 16) {
            wmma::fragment<wmma::matrix_a, 16, 16, 16, bf, wmma::row_major> af[4];
            wmma::fragment<wmma::matrix_b, 16, 16, 16, bf, wmma::row_major> bfr[4];
            #pragma unroll
            for (int i = 0; i < 4; i++)
                wmma::load_matrix_sync(af[i], &A_s[cur][wm * 64 + i * 16][kk], 40);
            #pragma unroll
            for (int j = 0; j < 4; j++)
                wmma::load_matrix_sync(bfr[j], &B_s[cur][kk][wn * 64 + j * 16], 136);
            #pragma unroll
            for (int i = 0; i < 4; i++)
                #pragma unroll
                for (int j = 0; j < 4; j++)
                    wmma::mma_sync(acc[i][j], af[i], bfr[j], acc[i][j]);
        }
        __syncthreads();
    }

    const bool is_q = (by < 2);
    #pragma unroll
    for (int ch = 0; ch < 2; ch++) {
        if (wm == ch) {
            #pragma unroll
            for (int i = 0; i < 4; i++)
                #pragma unroll
                for (int j = 0; j < 4; j++)
                    wmma::store_matrix_sync(&stage[i * 16][wn * 64 + j * 16],
                                            acc[i][j], 132, wmma::mem_row_major);
        }
        __syncthreads();
        if (is_q) {
            // column softmax per 32-row head block (2 blocks in this 64-row chunk)
            int col = tid;
            #pragma unroll
            for (int hb = 0; hb < 2; hb++) {
                int rbase = hb * 32;
                float vbuf[32];
                float m = -1e30f;
                #pragma unroll
                for (int rr = 0; rr < 32; rr++) {
                    float vv = stage[rbase + rr][col] + biasT[ch * 64 + rbase + rr];
                    vbuf[rr] = vv; m = fmaxf(m, vv);
                }
                float s = 0.f;
                #pragma unroll
                for (int rr = 0; rr < 32; rr++) { vbuf[rr] = __expf(vbuf[rr] - m); s += vbuf[rr]; }
                float inv = SCALE / s;
                #pragma unroll
                for (int rr = 0; rr < 32; rr++) stage[rbase + rr][col] = vbuf[rr] * inv;
            }
            __syncthreads();
        }
        for (int idx = tid; idx < 64 * 128; idx += 128) {
            int r = idx >> 7, cc = idx & 127;
            int e = by * 128 + ch * 64 + r;
            float v = stage[r][cc] + (is_q ? 0.f : biasT[ch * 64 + r]);
            g_qkv[(size_t)(b * E3 + e) * CT + (size_t)bx * 128 + cc] = __float2bfloat16(v);
        }
        __syncthreads();
    }
}

// ---------------- K4: ctx per (bc, h): ctx[fk][fv] = sum_t exp(k) * v/T ; S[fk] ----------------
__global__ __launch_bounds__(256) void ctx_kernel() {
    const int h = blockIdx.x & 7;
    const int bc = blockIdx.x >> 3;
    const int b = bc >> 6, c = bc & 63;
    const int tid = threadIdx.x;
    const int w = tid >> 5;

    const bf* gk = g_qkv + (size_t)(b * E3 + 256 + h * Ff) * CT + (size_t)c * Tt;
    const bf* gv = g_qkv + (size_t)(b * E3 + 512 + h * Ff) * CT + (size_t)c * Tt;

    __shared__ __align__(16) bf kbuf[32][136];
    __shared__ __align__(16) bf vbuf[32][136];
    __shared__ __align__(16) float stage[32][148];
    __shared__ float S_s[32];

    const int row = tid >> 3;      // 0..31
    const int lg  = tid & 7;       // 8 threads per row, 16 t each
    float s_local = 0.f;

    wmma::fragment<wmma::accumulator, 16, 16, 16, float> cacc[2][2];
    #pragma unroll
    for (int i = 0; i < 2; i++)
        #pragma unroll
        for (int j = 0; j < 2; j++) wmma::fill_fragment(cacc[i][j], 0.f);

    for (int tc = 0; tc < Tt; tc += 128) {
        __syncthreads();
        {
            const bf* kp = gk + (size_t)row * CT + tc + lg * 16;
            const bf* vp = gv + (size_t)row * CT + tc + lg * 16;
            #pragma unroll
            for (int q2 = 0; q2 < 2; q2++) {
                union { uint4 u; __nv_bfloat162 h2[4]; } kin, vin;
                kin.u = *(const uint4*)(kp + q2 * 8);
                vin.u = *(const uint4*)(vp + q2 * 8);
                #pragma unroll
                for (int u = 0; u < 4; u++) {
                    float2 kf = __bfloat1622float2(kin.h2[u]);
                    float2 vf = __bfloat1622float2(vin.h2[u]);
                    float e0 = __expf(kf.x), e1 = __expf(kf.y);
                    s_local += e0 + e1;
                    int cc = lg * 16 + q2 * 8 + u * 2;
                    kbuf[row][cc]     = __float2bfloat16(e0);
                    kbuf[row][cc + 1] = __float2bfloat16(e1);
                    vbuf[row][cc]     = __float2bfloat16(vf.x * (1.0f / 1024.0f));
                    vbuf[row][cc + 1] = __float2bfloat16(vf.y * (1.0f / 1024.0f));
                }
            }
        }
        __syncthreads();
        // warp w handles t-slice w*16
        wmma::fragment<wmma::matrix_a, 16, 16, 16, bf, wmma::row_major> af;
        wmma::fragment<wmma::matrix_b, 16, 16, 16, bf, wmma::col_major> bfr;
        #pragma unroll
        for (int i = 0; i < 2; i++) {
            wmma::load_matrix_sync(af, &kbuf[i * 16][w * 16], 136);
            #pragma unroll
            for (int j = 0; j < 2; j++) {
                wmma::load_matrix_sync(bfr, &vbuf[j * 16][w * 16], 136);
                wmma::mma_sync(cacc[i][j], af, bfr, cacc[i][j]);
            }
        }
    }

    // S reduce within 8-lane groups
    s_local += __shfl_xor_sync(~0u, s_local, 1);
    s_local += __shfl_xor_sync(~0u, s_local, 2);
    s_local += __shfl_xor_sync(~0u, s_local, 4);
    if (lg == 0) S_s[row] = s_local;

    // cross-warp reduction of 8 partial ctx tiles (slots at col q*36)
    auto storeP = [&](int q) {
        #pragma unroll
        for (int i = 0; i < 2; i++)
            #pragma unroll
            for (int j = 0; j < 2; j++)
                wmma::store_matrix_sync(&stage[i * 16][q * 36 + j * 16],
                                        cacc[i][j], 148, wmma::mem_row_major);
    };
    auto addP = [&](int q) {
        wmma::fragment<wmma::accumulator, 16, 16, 16, float> tmp;
        #pragma unroll
        for (int i = 0; i < 2; i++)
            #pragma unroll
            for (int j = 0; j < 2; j++) {
                wmma::load_matrix_sync(tmp, &stage[i * 16][q * 36 + j * 16],
                                       148, wmma::mem_row_major);
                for (int e = 0; e < tmp.num_elements; e++) cacc[i][j].x[e] += tmp.x[e];
            }
    };
    __syncthreads();
    if (w >= 4) storeP(w - 4);
    __syncthreads();
    if (w < 4) addP(w);
    __syncthreads();
    if (w == 2 || w == 3) storeP(w - 2);
    __syncthreads();
    if (w < 2) addP(w);
    __syncthreads();
    if (w == 1) storeP(0);
    __syncthreads();
    if (w == 0) { addP(0); storeP(0); }   // final ctx at stage[fk][fv]
    __syncthreads();

    for (int idx = tid; idx < 1024; idx += 256) {
        int fk = idx >> 5, fv = idx & 31;
        float val = stage[fk][fv] / S_s[fk];
        g_ctx[(((size_t)bc * Hh + h) * Ff + fv) * Ff + fk] = __float2bfloat16(val);
    }
}

// ---------------- K5: Mcat[bc] = W_out x blockdiag(ctx^T) ----------------
__global__ __launch_bounds__(256) void mcat_kernel() {
    int bc = blockIdx.x;
    __shared__ bf ctxs[8192];   // [h][fv][fk]
    int tid = threadIdx.x;
    for (int i = tid; i < 8192; i += 256) ctxs[i] = g_ctx[(size_t)bc * 8192 + i];
    __syncthreads();
    int e = tid;
    const bf* wrow = g_wout + e * Dm;
    #pragma unroll 1
    for (int h = 0; h < 8; h++) {
        float wv[32];
        #pragma unroll
        for (int fv = 0; fv < 32; fv++) wv[fv] = __bfloat162float(wrow[h * 32 + fv]);
        float o[32];
        #pragma unroll
        for (int fk = 0; fk < 32; fk++) o[fk] = 0.f;
        #pragma unroll
        for (int fv = 0; fv < 32; fv++) {
            float wf = wv[fv];
            const bf* cr = ctxs + h * 1024 + fv * 32;
            #pragma unroll
            for (int fk = 0; fk < 32; fk++) o[fk] += wf * __bfloat162float(cr[fk]);
        }
        __align__(16) bf ob[32];
        #pragma unroll
        for (int fk = 0; fk < 32; fk++) ob[fk] = __float2bfloat16(o[fk]);
        uint4* dst = (uint4*)(g_mcat + ((size_t)bc * Dm + e) * Dm + h * 32);
        const uint4* src = (const uint4*)ob;
        #pragma unroll
        for (int q2 = 0; q2 < 4; q2++) dst[q2] = src[q2];
    }
}

// ---------------- K6: out = Mcat[bc] @ q~ + out_b + x ----------------
__global__ __launch_bounds__(256) void final_gemm(const float* __restrict__ x,
                                                  const float* __restrict__ out_b,
                                                  float* __restrict__ out) {
    const int bx = blockIdx.x;   // t tile (8)
    const int by = blockIdx.y;   // e half (2)
    const int bc = blockIdx.z;   // 128
    const int b = bc >> 6, c = bc & 63;

    __shared__ __align__(16) char smem_raw[2 * 128 * 40 * 2 + 2 * 32 * 136 * 2];
    bf (*A_s)[128][40]  = (bf(*)[128][40])smem_raw;
    bf (*B_s)[32][136]  = (bf(*)[32][136])(smem_raw + 2 * 128 * 40 * 2);
    float (*stage)[132] = (float(*)[132])smem_raw;

    const int tid = threadIdx.x;
    const int w = tid >> 5;
    const int wm = w >> 2, wn = w & 3;

    const bf* Aptr = g_mcat + (size_t)bc * Dm * Dm + (size_t)by * 128 * Dm;
    const bf* Bptr = g_qkv + (size_t)b * E3 * CT + (size_t)c * Tt + (size_t)bx * 128;  // q~ rows 0..255

    wmma::fragment<wmma::accumulator, 16, 16, 16, float> acc[4][2];
    #pragma unroll
    for (int i = 0; i < 4; i++)
        #pragma unroll
        for (int j = 0; j < 2; j++) wmma::fill_fragment(acc[i][j], 0.0f);

    auto loadA = [&](int s, int k0) {
        #pragma unroll
        for (int it = 0; it < 2; it++) {
            int idx = tid + it * 256;
            int r = idx >> 2, c8 = (idx & 3) * 8;
            cp16(&A_s[s][r][c8], Aptr + (size_t)r * Dm + k0 + c8);
        }
    };
    auto loadB = [&](int s, int k0) {
        #pragma unroll
        for (int it = 0; it < 2; it++) {
            int idx = tid + it * 256;
            int r = idx >> 4, c8 = (idx & 15) * 8;
            cp16(&B_s[s][r][c8], Bptr + (size_t)(k0 + r) * CT + c8);
        }
    };

    loadA(0, 0); loadB(0, 0); CP_COMMIT();

    for (int ks = 0; ks < 8; ks++) {
        int cur = ks & 1;
        if (ks < 7) {
            loadA(cur ^ 1, (ks + 1) * 32);
            loadB(cur ^ 1, (ks + 1) * 32);
            CP_COMMIT();
            CP_WAIT1();
        } else {
            CP_WAIT0();
        }
        __syncthreads();
        #pragma unroll
        for (int kk = 0; kk < 32; kk += 16) {
            wmma::fragment<wmma::matrix_a, 16, 16, 16, bf, wmma::row_major> af[4];
            wmma::fragment<wmma::matrix_b, 16, 16, 16, bf, wmma::row_major> bfr[2];
            #pragma unroll
            for (int i = 0; i < 4; i++)
                wmma::load_matrix_sync(af[i], &A_s[cur][wm * 64 + i * 16][kk], 40);
            #pragma unroll
            for (int j = 0; j < 2; j++)
                wmma::load_matrix_sync(bfr[j], &B_s[cur][kk][wn * 32 + j * 16], 136);
            #pragma unroll
            for (int i = 0; i < 4; i++)
                #pragma unroll
                for (int j = 0; j < 2; j++)
                    wmma::mma_sync(acc[i][j], af[i], bfr[j], acc[i][j]);
        }
        __syncthreads();
    }

    #pragma unroll
    for (int ch = 0; ch < 2; ch++) {
        if (wm == ch) {
            #pragma unroll
            for (int i = 0; i < 4; i++)
                #pragma unroll
                for (int j = 0; j < 2; j++)
                    wmma::store_matrix_sync(&stage[i * 16][wn * 32 + j * 16],
                                            acc[i][j], 132, wmma::mem_row_major);
        }
        __syncthreads();
        for (int idx = tid; idx < 64 * 128; idx += 256) {
            int r = idx >> 7, cc = idx & 127;
            int e = by * 128 + ch * 64 + r;
            size_t gi = ((size_t)(b * Dm + e) * Cc + c) * Tt + (size_t)bx * 128 + cc;
            out[gi] = stage[r][cc] + out_b[e] + x[gi];
        }
        __syncthreads();
    }
}

// ---------------- launch ----------------
extern "C" void kernel_launch(void* const* d_in, const int* in_sizes, int n_in,
                              void* d_out, int out_size) {
    const float* x     = (const float*)d_in[0];
    const float* in_w  = (const float*)d_in[1];
    const float* in_b  = (const float*)d_in[2];
    const float* out_w = (const float*)d_in[3];
    const float* out_b = (const float*)d_in[4];
    float* out = (float*)d_out;

    stats_cvt<<<Bn * Dm, 256>>>(x);
    prep_weights<<<Bn * E3, 256>>>(in_w, in_b);
    conv_outw<<<Dm * Dm / 256, 256>>>(out_w);
    qkv_gemm<<<dim3(CT / 128, E3 / 128, Bn), 128>>>();
    ctx_kernel<<<Bn * Cc * Hh, 256>>>();
    mcat_kernel<<<Bn * Cc, 256>>>();
    final_gemm<<<dim3(Tt / 128, 2, Bn * Cc), 256>>>(x, out_b, out);
}

// round 8
// speedup vs baseline: 1.3745x; 1.0884x over previous
#include <cstdint>
#include <cuda_runtime.h>
#include <cuda_bf16.h>
#include <mma.h>

using namespace nvcuda;
typedef __nv_bfloat16 bf;

#define Bn 2
#define Dm 256
#define Cc 64
#define Tt 1024
#define Hh 8
#define Ff 32
#define CT 65536
#define E3 768
#define EPS 1e-5f
#define SCALE 0.1767766952966369f

// ---------------- scratch ----------------
__device__ __align__(128) bf g_xbf[(size_t)Bn * Dm * CT];            // 67 MB
__device__ __align__(128) bf g_qkv[(size_t)Bn * E3 * CT];            // q part = q~
__device__ __align__(128) bf g_weff[(size_t)Bn * E3 * Dm];
__device__ float g_mu[Bn * Dm];
__device__ float g_rstd[Bn * Dm];
__device__ float g_bias[Bn * E3];
__device__ __align__(128) bf g_wout[Dm * Dm];
__device__ __align__(128) bf g_ctx[(size_t)Bn * Cc * Hh * Ff * Ff];
__device__ __align__(128) bf g_mcat[(size_t)Bn * Cc * Dm * Dm];

// ---------------- cp.async ----------------
__device__ __forceinline__ void cp16(void* smem, const void* gmem) {
    unsigned s = (unsigned)__cvta_generic_to_shared(smem);
    asm volatile("cp.async.cg.shared.global [%0], [%1], 16;\n" :: "r"(s), "l"(gmem));
}
#define CP_COMMIT() asm volatile("cp.async.commit_group;\n")
#define CP_WAIT1()  asm volatile("cp.async.wait_group 1;\n")
#define CP_WAIT0()  asm volatile("cp.async.wait_group 0;\n")

// ---------------- K1: stats + convert x to bf16 ----------------
__global__ __launch_bounds__(256) void stats_cvt(const float* __restrict__ x) {
    size_t base = (size_t)blockIdx.x * CT;
    const float4* p = (const float4*)(x + base);
    bf* ob = g_xbf + base;
    float s = 0.f, ss = 0.f;
    for (int i = threadIdx.x; i < CT / 4; i += 256) {
        float4 v = p[i];
        s += v.x + v.y + v.z + v.w;
        ss += v.x * v.x + v.y * v.y + v.z * v.z + v.w * v.w;
        union { uint2 u; __nv_bfloat162 h[2]; } pk;
        pk.h[0] = __floats2bfloat162_rn(v.x, v.y);
        pk.h[1] = __floats2bfloat162_rn(v.z, v.w);
        *(uint2*)(ob + (size_t)i * 4) = pk.u;
    }
    __shared__ float rs[8], rss[8];
    for (int off = 16; off; off >>= 1) {
        s  += __shfl_down_sync(~0u, s, off);
        ss += __shfl_down_sync(~0u, ss, off);
    }
    int wid = threadIdx.x >> 5, lane = threadIdx.x & 31;
    if (lane == 0) { rs[wid] = s; rss[wid] = ss; }
    __syncthreads();
    if (threadIdx.x == 0) {
        float S = 0.f, SS = 0.f;
        for (int i = 0; i < 8; i++) { S += rs[i]; SS += rss[i]; }
        float mu = S / (float)CT;
        float var = SS / (float)CT - mu * mu;
        g_mu[blockIdx.x] = mu;
        g_rstd[blockIdx.x] = rsqrtf(var + EPS);
    }
}

// ---------------- K2: fold instance norm into weights ----------------
__global__ __launch_bounds__(256) void prep_weights(const float* __restrict__ in_w,
                                                    const float* __restrict__ in_b) {
    int be = blockIdx.x;
    int b = be / E3, e = be % E3;
    int d = threadIdx.x;
    float w = in_w[e * Dm + d];
    float r = g_rstd[b * Dm + d];
    float m = g_mu[b * Dm + d];
    float we = w * r;
    g_weff[(size_t)be * Dm + d] = __float2bfloat16(we);
    __shared__ float red[256];
    red[d] = we * m;
    __syncthreads();
    for (int s = 128; s > 0; s >>= 1) {
        if (d < s) red[d] += red[d + s];
        __syncthreads();
    }
    if (d == 0) g_bias[be] = in_b[e] - red[0];
}

__global__ __launch_bounds__(256) void conv_outw(const float* __restrict__ out_w) {
    int i = blockIdx.x * 256 + threadIdx.x;
    g_wout[i] = __float2bfloat16(out_w[i]);
}

// ---------------- K3: qkv GEMM, 128 thr, 64x64 warp tiles, K-chunk 64 ----------------
// grid (6 e-tiles [x, so blocks sharing a B tile are adjacent], 512 t-tiles, 2 b)
// dyn smem: A[2][128][72]bf @0 (36864), B[2][64][136]bf @36864 (34816),
//           stage f32[128][132] overlays @0 (67584), biasT @71680 (512). total 72192.
#define QKV_SB    36864
#define QKV_SBIAS 71680
#define QKV_SMEM  72192

__global__ __launch_bounds__(128) void qkv_gemm() {
    extern __shared__ __align__(16) char sm[];
    bf (*A_s)[128][72] = (bf(*)[128][72])sm;
    bf (*B_s)[64][136] = (bf(*)[64][136])(sm + QKV_SB);
    float (*stage)[132] = (float(*)[132])sm;
    float* biasT = (float*)(sm + QKV_SBIAS);

    const int et = blockIdx.x;   // e tile (6); et<2 => q
    const int tt = blockIdx.y;   // t tile (512)
    const int b  = blockIdx.z;

    const int tid = threadIdx.x;
    const int w = tid >> 5;
    const int wm = w >> 1, wn = w & 1;

    biasT[tid] = g_bias[b * E3 + et * 128 + tid];

    const bf* Aptr = g_weff + (size_t)(b * E3 + et * 128) * Dm;
    const bf* Bptr = g_xbf + (size_t)b * Dm * CT + (size_t)tt * 128;

    wmma::fragment<wmma::accumulator, 16, 16, 16, float> acc[4][4];
    #pragma unroll
    for (int i = 0; i < 4; i++)
        #pragma unroll
        for (int j = 0; j < 4; j++) wmma::fill_fragment(acc[i][j], 0.0f);

    auto loadA = [&](int s, int k0) {
        #pragma unroll
        for (int it = 0; it < 8; it++) {
            int idx = tid + it * 128;
            int r = idx >> 3, c8 = (idx & 7) * 8;
            cp16(&A_s[s][r][c8], Aptr + (size_t)r * Dm + k0 + c8);
        }
    };
    auto loadB = [&](int s, int k0) {
        #pragma unroll
        for (int it = 0; it < 8; it++) {
            int idx = tid + it * 128;
            int r = idx >> 4, c8 = (idx & 15) * 8;
            cp16(&B_s[s][r][c8], Bptr + (size_t)(k0 + r) * CT + c8);
        }
    };

    loadA(0, 0); loadB(0, 0); CP_COMMIT();

    #pragma unroll 1
    for (int ks = 0; ks < 4; ks++) {
        int cur = ks & 1;
        if (ks < 3) {
            loadA(cur ^ 1, (ks + 1) * 64);
            loadB(cur ^ 1, (ks + 1) * 64);
            CP_COMMIT();
            CP_WAIT1();
        } else {
            CP_WAIT0();
        }
        __syncthreads();
        #pragma unroll
        for (int kk = 0; kk < 64; kk += 16) {
            wmma::fragment<wmma::matrix_a, 16, 16, 16, bf, wmma::row_major> af[4];
            wmma::fragment<wmma::matrix_b, 16, 16, 16, bf, wmma::row_major> bfr[4];
            #pragma unroll
            for (int i = 0; i < 4; i++)
                wmma::load_matrix_sync(af[i], &A_s[cur][wm * 64 + i * 16][kk], 72);
            #pragma unroll
            for (int j = 0; j < 4; j++)
                wmma::load_matrix_sync(bfr[j], &B_s[cur][kk][wn * 64 + j * 16], 136);
            #pragma unroll
            for (int i = 0; i < 4; i++)
                #pragma unroll
                for (int j = 0; j < 4; j++)
                    wmma::mma_sync(acc[i][j], af[i], bfr[j], acc[i][j]);
        }
        __syncthreads();
    }

    // epilogue: buffers dead, overlay fp32 stage [128][132]
    #pragma unroll
    for (int i = 0; i < 4; i++)
        #pragma unroll
        for (int j = 0; j < 4; j++)
            wmma::store_matrix_sync(&stage[wm * 64 + i * 16][wn * 64 + j * 16],
                                    acc[i][j], 132, wmma::mem_row_major);
    __syncthreads();

    const bool is_q = (et < 2);
    if (is_q) {
        // column softmax per 32-row head block; bias folded in here
        int col = tid;
        #pragma unroll
        for (int hb = 0; hb < 4; hb++) {
            float vbuf[32];
            float m = -1e30f;
            #pragma unroll
            for (int rr = 0; rr < 32; rr++) {
                float vv = stage[hb * 32 + rr][col] + biasT[hb * 32 + rr];
                vbuf[rr] = vv; m = fmaxf(m, vv);
            }
            float s = 0.f;
            #pragma unroll
            for (int rr = 0; rr < 32; rr++) { vbuf[rr] = __expf(vbuf[rr] - m); s += vbuf[rr]; }
            float inv = SCALE / s;
            #pragma unroll
            for (int rr = 0; rr < 32; rr++)
                stage[hb * 32 + rr][col] = vbuf[rr] * inv;
        }
        __syncthreads();
    }

    // vectorized store: 8 bf16 (16B) per thread-iter
    #pragma unroll
    for (int it = 0; it < 16; it++) {
        int idx = tid + it * 128;
        int r = idx >> 4, c8 = (idx & 15) * 8;
        float badd = is_q ? 0.f : biasT[r];
        union { uint4 u; __nv_bfloat162 h2[4]; } o;
        #pragma unroll
        for (int u2 = 0; u2 < 4; u2++)
            o.h2[u2] = __floats2bfloat162_rn(stage[r][c8 + 2 * u2] + badd,
                                             stage[r][c8 + 2 * u2 + 1] + badd);
        *(uint4*)(g_qkv + (size_t)(b * E3 + et * 128 + r) * CT + (size_t)tt * 128 + c8) = o.u;
    }
}

// ---------------- K4: ctx per (bc, h) ----------------
__global__ __launch_bounds__(256) void ctx_kernel() {
    const int h = blockIdx.x & 7;
    const int bc = blockIdx.x >> 3;
    const int b = bc >> 6, c = bc & 63;
    const int tid = threadIdx.x;
    const int w = tid >> 5;

    const bf* gk = g_qkv + (size_t)(b * E3 + 256 + h * Ff) * CT + (size_t)c * Tt;
    const bf* gv = g_qkv + (size_t)(b * E3 + 512 + h * Ff) * CT + (size_t)c * Tt;

    __shared__ __align__(16) bf kbuf[32][136];
    __shared__ __align__(16) bf vbuf[32][136];
    __shared__ __align__(16) float stage[32][148];
    __shared__ float S_s[32];

    const int row = tid >> 3;
    const int lg  = tid & 7;
    float s_local = 0.f;

    wmma::fragment<wmma::accumulator, 16, 16, 16, float> cacc[2][2];
    #pragma unroll
    for (int i = 0; i < 2; i++)
        #pragma unroll
        for (int j = 0; j < 2; j++) wmma::fill_fragment(cacc[i][j], 0.f);

    for (int tc = 0; tc < Tt; tc += 128) {
        __syncthreads();
        {
            const bf* kp = gk + (size_t)row * CT + tc + lg * 16;
            const bf* vp = gv + (size_t)row * CT + tc + lg * 16;
            #pragma unroll
            for (int q2 = 0; q2 < 2; q2++) {
                union { uint4 u; __nv_bfloat162 h2[4]; } kin, vin;
                kin.u = *(const uint4*)(kp + q2 * 8);
                vin.u = *(const uint4*)(vp + q2 * 8);
                #pragma unroll
                for (int u = 0; u < 4; u++) {
                    float2 kf = __bfloat1622float2(kin.h2[u]);
                    float2 vf = __bfloat1622float2(vin.h2[u]);
                    float e0 = __expf(kf.x), e1 = __expf(kf.y);
                    s_local += e0 + e1;
                    int cc = lg * 16 + q2 * 8 + u * 2;
                    kbuf[row][cc]     = __float2bfloat16(e0);
                    kbuf[row][cc + 1] = __float2bfloat16(e1);
                    vbuf[row][cc]     = __float2bfloat16(vf.x * (1.0f / 1024.0f));
                    vbuf[row][cc + 1] = __float2bfloat16(vf.y * (1.0f / 1024.0f));
                }
            }
        }
        __syncthreads();
        wmma::fragment<wmma::matrix_a, 16, 16, 16, bf, wmma::row_major> af;
        wmma::fragment<wmma::matrix_b, 16, 16, 16, bf, wmma::col_major> bfr;
        #pragma unroll
        for (int i = 0; i < 2; i++) {
            wmma::load_matrix_sync(af, &kbuf[i * 16][w * 16], 136);
            #pragma unroll
            for (int j = 0; j < 2; j++) {
                wmma::load_matrix_sync(bfr, &vbuf[j * 16][w * 16], 136);
                wmma::mma_sync(cacc[i][j], af, bfr, cacc[i][j]);
            }
        }
    }

    s_local += __shfl_xor_sync(~0u, s_local, 1);
    s_local += __shfl_xor_sync(~0u, s_local, 2);
    s_local += __shfl_xor_sync(~0u, s_local, 4);
    if (lg == 0) S_s[row] = s_local;

    auto storeP = [&](int q) {
        #pragma unroll
        for (int i = 0; i < 2; i++)
            #pragma unroll
            for (int j = 0; j < 2; j++)
                wmma::store_matrix_sync(&stage[i * 16][q * 36 + j * 16],
                                        cacc[i][j], 148, wmma::mem_row_major);
    };
    auto addP = [&](int q) {
        wmma::fragment<wmma::accumulator, 16, 16, 16, float> tmp;
        #pragma unroll
        for (int i = 0; i < 2; i++)
            #pragma unroll
            for (int j = 0; j < 2; j++) {
                wmma::load_matrix_sync(tmp, &stage[i * 16][q * 36 + j * 16],
                                       148, wmma::mem_row_major);
                for (int e = 0; e < tmp.num_elements; e++) cacc[i][j].x[e] += tmp.x[e];
            }
    };
    __syncthreads();
    if (w >= 4) storeP(w - 4);
    __syncthreads();
    if (w < 4) addP(w);
    __syncthreads();
    if (w == 2 || w == 3) storeP(w - 2);
    __syncthreads();
    if (w < 2) addP(w);
    __syncthreads();
    if (w == 1) storeP(0);
    __syncthreads();
    if (w == 0) { addP(0); storeP(0); }
    __syncthreads();

    for (int idx = tid; idx < 1024; idx += 256) {
        int fk = idx >> 5, fv = idx & 31;
        float val = stage[fk][fv] / S_s[fk];
        g_ctx[(((size_t)bc * Hh + h) * Ff + fv) * Ff + fk] = __float2bfloat16(val);
    }
}

// ---------------- K5: Mcat ----------------
__global__ __launch_bounds__(256) void mcat_kernel() {
    int bc = blockIdx.x;
    __shared__ bf ctxs[8192];
    int tid = threadIdx.x;
    for (int i = tid; i < 8192; i += 256) ctxs[i] = g_ctx[(size_t)bc * 8192 + i];
    __syncthreads();
    int e = tid;
    const bf* wrow = g_wout + e * Dm;
    #pragma unroll 1
    for (int h = 0; h < 8; h++) {
        float wv[32];
        #pragma unroll
        for (int fv = 0; fv < 32; fv++) wv[fv] = __bfloat162float(wrow[h * 32 + fv]);
        float o[32];
        #pragma unroll
        for (int fk = 0; fk < 32; fk++) o[fk] = 0.f;
        #pragma unroll
        for (int fv = 0; fv < 32; fv++) {
            float wf = wv[fv];
            const bf* cr = ctxs + h * 1024 + fv * 32;
            #pragma unroll
            for (int fk = 0; fk < 32; fk++) o[fk] += wf * __bfloat162float(cr[fk]);
        }
        __align__(16) bf ob[32];
        #pragma unroll
        for (int fk = 0; fk < 32; fk++) ob[fk] = __float2bfloat16(o[fk]);
        uint4* dst = (uint4*)(g_mcat + ((size_t)bc * Dm + e) * Dm + h * 32);
        const uint4* src = (const uint4*)ob;
        #pragma unroll
        for (int q2 = 0; q2 < 4; q2++) dst[q2] = src[q2];
    }
}

// ---------------- K6: out = Mcat[bc] @ q~ + out_b + x ----------------
__global__ __launch_bounds__(256) void final_gemm(const float* __restrict__ x,
                                                  const float* __restrict__ out_b,
                                                  float* __restrict__ out) {
    const int bx = blockIdx.x;
    const int by = blockIdx.y;
    const int bc = blockIdx.z;
    const int b = bc >> 6, c = bc & 63;

    __shared__ __align__(16) char smem_raw[2 * 128 * 40 * 2 + 2 * 32 * 136 * 2];
    bf (*A_s)[128][40]  = (bf(*)[128][40])smem_raw;
    bf (*B_s)[32][136]  = (bf(*)[32][136])(smem_raw + 2 * 128 * 40 * 2);
    float (*stage)[132] = (float(*)[132])smem_raw;

    const int tid = threadIdx.x;
    const int w = tid >> 5;
    const int wm = w >> 2, wn = w & 3;

    const bf* Aptr = g_mcat + (size_t)bc * Dm * Dm + (size_t)by * 128 * Dm;
    const bf* Bptr = g_qkv + (size_t)b * E3 * CT + (size_t)c * Tt + (size_t)bx * 128;

    wmma::fragment<wmma::accumulator, 16, 16, 16, float> acc[4][2];
    #pragma unroll
    for (int i = 0; i < 4; i++)
        #pragma unroll
        for (int j = 0; j < 2; j++) wmma::fill_fragment(acc[i][j], 0.0f);

    auto loadA = [&](int s, int k0) {
        #pragma unroll
        for (int it = 0; it < 2; it++) {
            int idx = tid + it * 256;
            int r = idx >> 2, c8 = (idx & 3) * 8;
            cp16(&A_s[s][r][c8], Aptr + (size_t)r * Dm + k0 + c8);
        }
    };
    auto loadB = [&](int s, int k0) {
        #pragma unroll
        for (int it = 0; it < 2; it++) {
            int idx = tid + it * 256;
            int r = idx >> 4, c8 = (idx & 15) * 8;
            cp16(&B_s[s][r][c8], Bptr + (size_t)(k0 + r) * CT + c8);
        }
    };

    loadA(0, 0); loadB(0, 0); CP_COMMIT();

    for (int ks = 0; ks < 8; ks++) {
        int cur = ks & 1;
        if (ks < 7) {
            loadA(cur ^ 1, (ks + 1) * 32);
            loadB(cur ^ 1, (ks + 1) * 32);
            CP_COMMIT();
            CP_WAIT1();
        } else {
            CP_WAIT0();
        }
        __syncthreads();
        #pragma unroll
        for (int kk = 0; kk < 32; kk += 16) {
            wmma::fragment<wmma::matrix_a, 16, 16, 16, bf, wmma::row_major> af[4];
            wmma::fragment<wmma::matrix_b, 16, 16, 16, bf, wmma::row_major> bfr[2];
            #pragma unroll
            for (int i = 0; i < 4; i++)
                wmma::load_matrix_sync(af[i], &A_s[cur][wm * 64 + i * 16][kk], 40);
            #pragma unroll
            for (int j = 0; j < 2; j++)
                wmma::load_matrix_sync(bfr[j], &B_s[cur][kk][wn * 32 + j * 16], 136);
            #pragma unroll
            for (int i = 0; i < 4; i++)
                #pragma unroll
                for (int j = 0; j < 2; j++)
                    wmma::mma_sync(acc[i][j], af[i], bfr[j], acc[i][j]);
        }
        __syncthreads();
    }

    #pragma unroll
    for (int ch = 0; ch < 2; ch++) {
        if (wm == ch) {
            #pragma unroll
            for (int i = 0; i < 4; i++)
                #pragma unroll
                for (int j = 0; j < 2; j++)
                    wmma::store_matrix_sync(&stage[i * 16][wn * 32 + j * 16],
                                            acc[i][j], 132, wmma::mem_row_major);
        }
        __syncthreads();
        for (int idx = tid; idx < 64 * 128; idx += 256) {
            int r = idx >> 7, cc = idx & 127;
            int e = by * 128 + ch * 64 + r;
            size_t gi = ((size_t)(b * Dm + e) * Cc + c) * Tt + (size_t)bx * 128 + cc;
            out[gi] = stage[r][cc] + out_b[e] + x[gi];
        }
        __syncthreads();
    }
}

// ---------------- launch ----------------
extern "C" void kernel_launch(void* const* d_in, const int* in_sizes, int n_in,
                              void* d_out, int out_size) {
    const float* x     = (const float*)d_in[0];
    const float* in_w  = (const float*)d_in[1];
    const float* in_b  = (const float*)d_in[2];
    const float* out_w = (const float*)d_in[3];
    const float* out_b = (const float*)d_in[4];
    float* out = (float*)d_out;

    cudaFuncSetAttribute(qkv_gemm, cudaFuncAttributeMaxDynamicSharedMemorySize, QKV_SMEM);

    stats_cvt<<<Bn * Dm, 256>>>(x);
    prep_weights<<<Bn * E3, 256>>>(in_w, in_b);
    conv_outw<<<Dm * Dm / 256, 256>>>(out_w);
    qkv_gemm<<<dim3(6, CT / 128, Bn), 128, QKV_SMEM>>>();
    ctx_kernel<<<Bn * Cc * Hh, 256>>>();
    mcat_kernel<<<Bn * Cc, 256>>>();
    final_gemm<<<dim3(Tt / 128, 2, Bn * Cc), 256>>>(x, out_b, out);
}

// round 9
// speedup vs baseline: 1.3991x; 1.0179x over previous
#include <cstdint>
#include <cuda_runtime.h>
#include <cuda_bf16.h>
#include <mma.h>

using namespace nvcuda;
typedef __nv_bfloat16 bf;

#define Bn 2
#define Dm 256
#define Cc 64
#define Tt 1024
#define Hh 8
#define Ff 32
#define CT 65536
#define E3 768
#define EPS 1e-5f
#define SCALE 0.1767766952966369f

// ---------------- scratch ----------------
__device__ __align__(128) bf g_xbf[(size_t)Bn * Dm * CT];            // 67 MB
__device__ __align__(128) bf g_qkv[(size_t)Bn * E3 * CT];            // q~ / exp(k) / v/T
__device__ __align__(128) bf g_weff[(size_t)Bn * E3 * Dm];
__device__ float g_mu[Bn * Dm];
__device__ float g_rstd[Bn * Dm];
__device__ float g_bias[Bn * E3];
__device__ __align__(128) bf g_wout[Dm * Dm];
__device__ __align__(128) bf g_ctx[(size_t)Bn * Cc * Hh * Ff * Ff];
__device__ __align__(128) bf g_mcat[(size_t)Bn * Cc * Dm * Dm];

// ---------------- cp.async ----------------
__device__ __forceinline__ void cp16(void* smem, const void* gmem) {
    unsigned s = (unsigned)__cvta_generic_to_shared(smem);
    asm volatile("cp.async.cg.shared.global [%0], [%1], 16;\n" :: "r"(s), "l"(gmem));
}
#define CP_COMMIT() asm volatile("cp.async.commit_group;\n")
#define CP_WAIT1()  asm volatile("cp.async.wait_group 1;\n")
#define CP_WAIT0()  asm volatile("cp.async.wait_group 0;\n")

// ---------------- K1: stats + convert x to bf16 ----------------
__global__ __launch_bounds__(256) void stats_cvt(const float* __restrict__ x) {
    size_t base = (size_t)blockIdx.x * CT;
    const float4* p = (const float4*)(x + base);
    bf* ob = g_xbf + base;
    float s = 0.f, ss = 0.f;
    for (int i = threadIdx.x; i < CT / 4; i += 256) {
        float4 v = p[i];
        s += v.x + v.y + v.z + v.w;
        ss += v.x * v.x + v.y * v.y + v.z * v.z + v.w * v.w;
        union { uint2 u; __nv_bfloat162 h[2]; } pk;
        pk.h[0] = __floats2bfloat162_rn(v.x, v.y);
        pk.h[1] = __floats2bfloat162_rn(v.z, v.w);
        *(uint2*)(ob + (size_t)i * 4) = pk.u;
    }
    __shared__ float rs[8], rss[8];
    for (int off = 16; off; off >>= 1) {
        s  += __shfl_down_sync(~0u, s, off);
        ss += __shfl_down_sync(~0u, ss, off);
    }
    int wid = threadIdx.x >> 5, lane = threadIdx.x & 31;
    if (lane == 0) { rs[wid] = s; rss[wid] = ss; }
    __syncthreads();
    if (threadIdx.x == 0) {
        float S = 0.f, SS = 0.f;
        for (int i = 0; i < 8; i++) { S += rs[i]; SS += rss[i]; }
        float mu = S / (float)CT;
        float var = SS / (float)CT - mu * mu;
        g_mu[blockIdx.x] = mu;
        g_rstd[blockIdx.x] = rsqrtf(var + EPS);
    }
}

// ---------------- K2: fold instance norm into weights ----------------
__global__ __launch_bounds__(256) void prep_weights(const float* __restrict__ in_w,
                                                    const float* __restrict__ in_b) {
    int be = blockIdx.x;
    int b = be / E3, e = be % E3;
    int d = threadIdx.x;
    float w = in_w[e * Dm + d];
    float r = g_rstd[b * Dm + d];
    float m = g_mu[b * Dm + d];
    float we = w * r;
    g_weff[(size_t)be * Dm + d] = __float2bfloat16(we);
    __shared__ float red[256];
    red[d] = we * m;
    __syncthreads();
    for (int s = 128; s > 0; s >>= 1) {
        if (d < s) red[d] += red[d + s];
        __syncthreads();
    }
    if (d == 0) g_bias[be] = in_b[e] - red[0];
}

__global__ __launch_bounds__(256) void conv_outw(const float* __restrict__ out_w) {
    int i = blockIdx.x * 256 + threadIdx.x;
    g_wout[i] = __float2bfloat16(out_w[i]);
}

// ---------------- K3: qkv GEMM, 3-stage pipeline, 1 barrier/chunk ----------------
// grid (6 e-tiles, 512 t-tiles, 2 b). 128 threads, 64x64 warp tiles, K-chunk 64.
// dyn smem: A[3][128][72]bf @0 (55296), B[3][64][136]bf @55296 (52224),
//           biasT @107520 (512). stage f32[128][132] overlays @0. total 108032.
#define QKV_SB    55296
#define QKV_SBIAS 107520
#define QKV_SMEM  108032

__global__ __launch_bounds__(128) void qkv_gemm() {
    extern __shared__ __align__(16) char sm[];
    bf (*A_s)[128][72] = (bf(*)[128][72])sm;
    bf (*B_s)[64][136] = (bf(*)[64][136])(sm + QKV_SB);
    float (*stage)[132] = (float(*)[132])sm;
    float* biasT = (float*)(sm + QKV_SBIAS);

    const int et = blockIdx.x;   // e tile (6); 0-1 q, 2-3 k, 4-5 v
    const int tt = blockIdx.y;   // t tile (512)
    const int b  = blockIdx.z;

    const int tid = threadIdx.x;
    const int w = tid >> 5;
    const int wm = w >> 1, wn = w & 1;

    biasT[tid] = g_bias[b * E3 + et * 128 + tid];

    const bf* Aptr = g_weff + (size_t)(b * E3 + et * 128) * Dm;
    const bf* Bptr = g_xbf + (size_t)b * Dm * CT + (size_t)tt * 128;

    wmma::fragment<wmma::accumulator, 16, 16, 16, float> acc[4][4];
    #pragma unroll
    for (int i = 0; i < 4; i++)
        #pragma unroll
        for (int j = 0; j < 4; j++) wmma::fill_fragment(acc[i][j], 0.0f);

    auto loadA = [&](int s, int k0) {
        #pragma unroll
        for (int it = 0; it < 8; it++) {
            int idx = tid + it * 128;
            int r = idx >> 3, c8 = (idx & 7) * 8;
            cp16(&A_s[s][r][c8], Aptr + (size_t)r * Dm + k0 + c8);
        }
    };
    auto loadB = [&](int s, int k0) {
        #pragma unroll
        for (int it = 0; it < 8; it++) {
            int idx = tid + it * 128;
            int r = idx >> 4, c8 = (idx & 15) * 8;
            cp16(&B_s[s][r][c8], Bptr + (size_t)(k0 + r) * CT + c8);
        }
    };
    auto mma_chunk = [&](int st) {
        #pragma unroll
        for (int kk = 0; kk < 64; kk += 16) {
            wmma::fragment<wmma::matrix_a, 16, 16, 16, bf, wmma::row_major> af[4];
            wmma::fragment<wmma::matrix_b, 16, 16, 16, bf, wmma::row_major> bfr[4];
            #pragma unroll
            for (int i = 0; i < 4; i++)
                wmma::load_matrix_sync(af[i], &A_s[st][wm * 64 + i * 16][kk], 72);
            #pragma unroll
            for (int j = 0; j < 4; j++)
                wmma::load_matrix_sync(bfr[j], &B_s[st][kk][wn * 64 + j * 16], 136);
            #pragma unroll
            for (int i = 0; i < 4; i++)
                #pragma unroll
                for (int j = 0; j < 4; j++)
                    wmma::mma_sync(acc[i][j], af[i], bfr[j], acc[i][j]);
        }
    };

    // 3-stage pipeline: one barrier per chunk.
    loadA(0, 0);   loadB(0, 0);   CP_COMMIT();
    loadA(1, 64);  loadB(1, 64);  CP_COMMIT();

    // ks=0
    CP_WAIT1(); __syncthreads();
    mma_chunk(0);
    loadA(2, 128); loadB(2, 128); CP_COMMIT();
    // ks=1
    CP_WAIT1(); __syncthreads();
    mma_chunk(1);
    loadA(0, 192); loadB(0, 192); CP_COMMIT();
    // ks=2
    CP_WAIT1(); __syncthreads();
    mma_chunk(2);
    // ks=3
    CP_WAIT0(); __syncthreads();
    mma_chunk(0);

    __syncthreads();   // buffers dead; overlay fp32 stage

    #pragma unroll
    for (int i = 0; i < 4; i++)
        #pragma unroll
        for (int j = 0; j < 4; j++)
            wmma::store_matrix_sync(&stage[wm * 64 + i * 16][wn * 64 + j * 16],
                                    acc[i][j], 132, wmma::mem_row_major);
    __syncthreads();

    if (et < 2) {
        // q: column softmax per 32-row head block; bias folded here
        int col = tid;
        #pragma unroll
        for (int hb = 0; hb < 4; hb++) {
            float vbuf[32];
            float m = -1e30f;
            #pragma unroll
            for (int rr = 0; rr < 32; rr++) {
                float vv = stage[hb * 32 + rr][col] + biasT[hb * 32 + rr];
                vbuf[rr] = vv; m = fmaxf(m, vv);
            }
            float s = 0.f;
            #pragma unroll
            for (int rr = 0; rr < 32; rr++) { vbuf[rr] = __expf(vbuf[rr] - m); s += vbuf[rr]; }
            float inv = SCALE / s;
            #pragma unroll
            for (int rr = 0; rr < 32; rr++)
                stage[hb * 32 + rr][col] = vbuf[rr] * inv;
        }
        __syncthreads();
        #pragma unroll
        for (int it = 0; it < 16; it++) {
            int idx = tid + it * 128;
            int r = idx >> 4, c8 = (idx & 15) * 8;
            union { uint4 u; __nv_bfloat162 h2[4]; } o;
            #pragma unroll
            for (int u2 = 0; u2 < 4; u2++)
                o.h2[u2] = __floats2bfloat162_rn(stage[r][c8 + 2 * u2], stage[r][c8 + 2 * u2 + 1]);
            *(uint4*)(g_qkv + (size_t)(b * E3 + et * 128 + r) * CT + (size_t)tt * 128 + c8) = o.u;
        }
    } else if (et < 4) {
        // k: write exp(k + bias) (unnormalized; S computed in ctx)
        #pragma unroll
        for (int it = 0; it < 16; it++) {
            int idx = tid + it * 128;
            int r = idx >> 4, c8 = (idx & 15) * 8;
            float badd = biasT[r];
            union { uint4 u; __nv_bfloat162 h2[4]; } o;
            #pragma unroll
            for (int u2 = 0; u2 < 4; u2++)
                o.h2[u2] = __floats2bfloat162_rn(__expf(stage[r][c8 + 2 * u2] + badd),
                                                 __expf(stage[r][c8 + 2 * u2 + 1] + badd));
            *(uint4*)(g_qkv + (size_t)(b * E3 + et * 128 + r) * CT + (size_t)tt * 128 + c8) = o.u;
        }
    } else {
        // v: write (v + bias) / T
        #pragma unroll
        for (int it = 0; it < 16; it++) {
            int idx = tid + it * 128;
            int r = idx >> 4, c8 = (idx & 15) * 8;
            float badd = biasT[r];
            union { uint4 u; __nv_bfloat162 h2[4]; } o;
            #pragma unroll
            for (int u2 = 0; u2 < 4; u2++)
                o.h2[u2] = __floats2bfloat162_rn((stage[r][c8 + 2 * u2] + badd) * (1.0f / 1024.0f),
                                                 (stage[r][c8 + 2 * u2 + 1] + badd) * (1.0f / 1024.0f));
            *(uint4*)(g_qkv + (size_t)(b * E3 + et * 128 + r) * CT + (size_t)tt * 128 + c8) = o.u;
        }
    }
}

// ---------------- K4: ctx per (bc, h): values pre-exponentiated/scaled ----------------
__global__ __launch_bounds__(256) void ctx_kernel() {
    const int h = blockIdx.x & 7;
    const int bc = blockIdx.x >> 3;
    const int b = bc >> 6, c = bc & 63;
    const int tid = threadIdx.x;
    const int w = tid >> 5;

    const bf* gk = g_qkv + (size_t)(b * E3 + 256 + h * Ff) * CT + (size_t)c * Tt;
    const bf* gv = g_qkv + (size_t)(b * E3 + 512 + h * Ff) * CT + (size_t)c * Tt;

    __shared__ __align__(16) bf kbuf[32][136];
    __shared__ __align__(16) bf vbuf[32][136];
    __shared__ __align__(16) float stage[32][148];
    __shared__ float S_s[32];

    const int row = tid >> 3;
    const int lg  = tid & 7;
    float s_local = 0.f;

    wmma::fragment<wmma::accumulator, 16, 16, 16, float> cacc[2][2];
    #pragma unroll
    for (int i = 0; i < 2; i++)
        #pragma unroll
        for (int j = 0; j < 2; j++) wmma::fill_fragment(cacc[i][j], 0.f);

    for (int tc = 0; tc < Tt; tc += 128) {
        __syncthreads();
        {
            const bf* kp = gk + (size_t)row * CT + tc + lg * 16;
            const bf* vp = gv + (size_t)row * CT + tc + lg * 16;
            #pragma unroll
            for (int q2 = 0; q2 < 2; q2++) {
                union { uint4 u; __nv_bfloat162 h2[4]; } kin;
                kin.u = *(const uint4*)(kp + q2 * 8);
                *(uint4*)&kbuf[row][lg * 16 + q2 * 8] = kin.u;
                #pragma unroll
                for (int u = 0; u < 4; u++) {
                    float2 kf = __bfloat1622float2(kin.h2[u]);
                    s_local += kf.x + kf.y;
                }
                *(uint4*)&vbuf[row][lg * 16 + q2 * 8] = *(const uint4*)(vp + q2 * 8);
            }
        }
        __syncthreads();
        wmma::fragment<wmma::matrix_a, 16, 16, 16, bf, wmma::row_major> af;
        wmma::fragment<wmma::matrix_b, 16, 16, 16, bf, wmma::col_major> bfr;
        #pragma unroll
        for (int i = 0; i < 2; i++) {
            wmma::load_matrix_sync(af, &kbuf[i * 16][w * 16], 136);
            #pragma unroll
            for (int j = 0; j < 2; j++) {
                wmma::load_matrix_sync(bfr, &vbuf[j * 16][w * 16], 136);
                wmma::mma_sync(cacc[i][j], af, bfr, cacc[i][j]);
            }
        }
    }

    s_local += __shfl_xor_sync(~0u, s_local, 1);
    s_local += __shfl_xor_sync(~0u, s_local, 2);
    s_local += __shfl_xor_sync(~0u, s_local, 4);
    if (lg == 0) S_s[row] = s_local;

    auto storeP = [&](int q) {
        #pragma unroll
        for (int i = 0; i < 2; i++)
            #pragma unroll
            for (int j = 0; j < 2; j++)
                wmma::store_matrix_sync(&stage[i * 16][q * 36 + j * 16],
                                        cacc[i][j], 148, wmma::mem_row_major);
    };
    auto addP = [&](int q) {
        wmma::fragment<wmma::accumulator, 16, 16, 16, float> tmp;
        #pragma unroll
        for (int i = 0; i < 2; i++)
            #pragma unroll
            for (int j = 0; j < 2; j++) {
                wmma::load_matrix_sync(tmp, &stage[i * 16][q * 36 + j * 16],
                                       148, wmma::mem_row_major);
                for (int e = 0; e < tmp.num_elements; e++) cacc[i][j].x[e] += tmp.x[e];
            }
    };
    __syncthreads();
    if (w >= 4) storeP(w - 4);
    __syncthreads();
    if (w < 4) addP(w);
    __syncthreads();
    if (w == 2 || w == 3) storeP(w - 2);
    __syncthreads();
    if (w < 2) addP(w);
    __syncthreads();
    if (w == 1) storeP(0);
    __syncthreads();
    if (w == 0) { addP(0); storeP(0); }
    __syncthreads();

    for (int idx = tid; idx < 1024; idx += 256) {
        int fk = idx >> 5, fv = idx & 31;
        float val = stage[fk][fv] / S_s[fk];
        g_ctx[(((size_t)bc * Hh + h) * Ff + fv) * Ff + fk] = __float2bfloat16(val);
    }
}

// ---------------- K5: Mcat ----------------
__global__ __launch_bounds__(256) void mcat_kernel() {
    int bc = blockIdx.x;
    __shared__ bf ctxs[8192];
    int tid = threadIdx.x;
    for (int i = tid; i < 8192; i += 256) ctxs[i] = g_ctx[(size_t)bc * 8192 + i];
    __syncthreads();
    int e = tid;
    const bf* wrow = g_wout + e * Dm;
    #pragma unroll 1
    for (int h = 0; h < 8; h++) {
        float wv[32];
        #pragma unroll
        for (int fv = 0; fv < 32; fv++) wv[fv] = __bfloat162float(wrow[h * 32 + fv]);
        float o[32];
        #pragma unroll
        for (int fk = 0; fk < 32; fk++) o[fk] = 0.f;
        #pragma unroll
        for (int fv = 0; fv < 32; fv++) {
            float wf = wv[fv];
            const bf* cr = ctxs + h * 1024 + fv * 32;
            #pragma unroll
            for (int fk = 0; fk < 32; fk++) o[fk] += wf * __bfloat162float(cr[fk]);
        }
        __align__(16) bf ob[32];
        #pragma unroll
        for (int fk = 0; fk < 32; fk++) ob[fk] = __float2bfloat16(o[fk]);
        uint4* dst = (uint4*)(g_mcat + ((size_t)bc * Dm + e) * Dm + h * 32);
        const uint4* src = (const uint4*)ob;
        #pragma unroll
        for (int q2 = 0; q2 < 4; q2++) dst[q2] = src[q2];
    }
}

// ---------------- K6: out = Mcat[bc] @ q~ + out_b + x ----------------
__global__ __launch_bounds__(256) void final_gemm(const float* __restrict__ x,
                                                  const float* __restrict__ out_b,
                                                  float* __restrict__ out) {
    const int bx = blockIdx.x;
    const int by = blockIdx.y;
    const int bc = blockIdx.z;
    const int b = bc >> 6, c = bc & 63;

    __shared__ __align__(16) char smem_raw[2 * 128 * 40 * 2 + 2 * 32 * 136 * 2];
    bf (*A_s)[128][40]  = (bf(*)[128][40])smem_raw;
    bf (*B_s)[32][136]  = (bf(*)[32][136])(smem_raw + 2 * 128 * 40 * 2);
    float (*stage)[132] = (float(*)[132])smem_raw;

    const int tid = threadIdx.x;
    const int w = tid >> 5;
    const int wm = w >> 2, wn = w & 3;

    const bf* Aptr = g_mcat + (size_t)bc * Dm * Dm + (size_t)by * 128 * Dm;
    const bf* Bptr = g_qkv + (size_t)b * E3 * CT + (size_t)c * Tt + (size_t)bx * 128;

    wmma::fragment<wmma::accumulator, 16, 16, 16, float> acc[4][2];
    #pragma unroll
    for (int i = 0; i < 4; i++)
        #pragma unroll
        for (int j = 0; j < 2; j++) wmma::fill_fragment(acc[i][j], 0.0f);

    auto loadA = [&](int s, int k0) {
        #pragma unroll
        for (int it = 0; it < 2; it++) {
            int idx = tid + it * 256;
            int r = idx >> 2, c8 = (idx & 3) * 8;
            cp16(&A_s[s][r][c8], Aptr + (size_t)r * Dm + k0 + c8);
        }
    };
    auto loadB = [&](int s, int k0) {
        #pragma unroll
        for (int it = 0; it < 2; it++) {
            int idx = tid + it * 256;
            int r = idx >> 4, c8 = (idx & 15) * 8;
            cp16(&B_s[s][r][c8], Bptr + (size_t)(k0 + r) * CT + c8);
        }
    };

    loadA(0, 0); loadB(0, 0); CP_COMMIT();

    for (int ks = 0; ks < 8; ks++) {
        int cur = ks & 1;
        if (ks < 7) {
            loadA(cur ^ 1, (ks + 1) * 32);
            loadB(cur ^ 1, (ks + 1) * 32);
            CP_COMMIT();
            CP_WAIT1();
        } else {
            CP_WAIT0();
        }
        __syncthreads();
        #pragma unroll
        for (int kk = 0; kk < 32; kk += 16) {
            wmma::fragment<wmma::matrix_a, 16, 16, 16, bf, wmma::row_major> af[4];
            wmma::fragment<wmma::matrix_b, 16, 16, 16, bf, wmma::row_major> bfr[2];
            #pragma unroll
            for (int i = 0; i < 4; i++)
                wmma::load_matrix_sync(af[i], &A_s[cur][wm * 64 + i * 16][kk], 40);
            #pragma unroll
            for (int j = 0; j < 2; j++)
                wmma::load_matrix_sync(bfr[j], &B_s[cur][kk][wn * 32 + j * 16], 136);
            #pragma unroll
            for (int i = 0; i < 4; i++)
                #pragma unroll
                for (int j = 0; j < 2; j++)
                    wmma::mma_sync(acc[i][j], af[i], bfr[j], acc[i][j]);
        }
        __syncthreads();
    }

    #pragma unroll
    for (int ch = 0; ch < 2; ch++) {
        if (wm == ch) {
            #pragma unroll
            for (int i = 0; i < 4; i++)
                #pragma unroll
                for (int j = 0; j < 2; j++)
                    wmma::store_matrix_sync(&stage[i * 16][wn * 32 + j * 16],
                                            acc[i][j], 132, wmma::mem_row_major);
        }
        __syncthreads();
        for (int idx = tid; idx < 64 * 128; idx += 256) {
            int r = idx >> 7, cc = idx & 127;
            int e = by * 128 + ch * 64 + r;
            size_t gi = ((size_t)(b * Dm + e) * Cc + c) * Tt + (size_t)bx * 128 + cc;
            out[gi] = stage[r][cc] + out_b[e] + x[gi];
        }
        __syncthreads();
    }
}

// ---------------- launch ----------------
extern "C" void kernel_launch(void* const* d_in, const int* in_sizes, int n_in,
                              void* d_out, int out_size) {
    const float* x     = (const float*)d_in[0];
    const float* in_w  = (const float*)d_in[1];
    const float* in_b  = (const float*)d_in[2];
    const float* out_w = (const float*)d_in[3];
    const float* out_b = (const float*)d_in[4];
    float* out = (float*)d_out;

    cudaFuncSetAttribute(qkv_gemm, cudaFuncAttributeMaxDynamicSharedMemorySize, QKV_SMEM);

    stats_cvt<<<Bn * Dm, 256>>>(x);
    prep_weights<<<Bn * E3, 256>>>(in_w, in_b);
    conv_outw<<<Dm * Dm / 256, 256>>>(out_w);
    qkv_gemm<<<dim3(6, CT / 128, Bn), 128, QKV_SMEM>>>();
    ctx_kernel<<<Bn * Cc * Hh, 256>>>();
    mcat_kernel<<<Bn * Cc, 256>>>();
    final_gemm<<<dim3(Tt / 128, 2, Bn * Cc), 256>>>(x, out_b, out);
}

// round 10
// speedup vs baseline: 1.5388x; 1.0999x over previous
#include <cstdint>
#include <cuda_runtime.h>
#include <cuda_bf16.h>
#include <mma.h>

using namespace nvcuda;
typedef __nv_bfloat16 bf;

#define Bn 2
#define Dm 256
#define Cc 64
#define Tt 1024
#define Hh 8
#define Ff 32
#define CT 65536
#define E3 768
#define EPS 1e-5f
#define SCALE 0.1767766952966369f

// ---------------- scratch ----------------
__device__ __align__(128) bf g_xbf[(size_t)Bn * Dm * CT];      // 67 MB
__device__ __align__(128) bf g_qt[(size_t)Bn * Dm * CT];       // q~ only, 67 MB
__device__ __align__(128) bf g_weff[(size_t)Bn * E3 * Dm];
__device__ float g_mu[Bn * Dm];
__device__ float g_rstd[Bn * Dm];
__device__ float g_bias[Bn * E3];
__device__ __align__(128) bf g_wout[Dm * Dm];
__device__ __align__(128) float g_ctxp[(size_t)Bn * Cc * 8 * Hh * Ff * Ff];  // 33.5 MB partials
__device__ __align__(128) float g_Sp[(size_t)Bn * Cc * 8 * 256];             // 1 MB partial S
__device__ __align__(128) bf g_mcat[(size_t)Bn * Cc * Dm * Dm];

// ---------------- cp.async ----------------
__device__ __forceinline__ void cp16(void* smem, const void* gmem) {
    unsigned s = (unsigned)__cvta_generic_to_shared(smem);
    asm volatile("cp.async.cg.shared.global [%0], [%1], 16;\n" :: "r"(s), "l"(gmem));
}
#define CP_COMMIT() asm volatile("cp.async.commit_group;\n")
#define CP_WAIT1()  asm volatile("cp.async.wait_group 1;\n")
#define CP_WAIT0()  asm volatile("cp.async.wait_group 0;\n")

// ---------------- K1: stats + convert x to bf16 ----------------
__global__ __launch_bounds__(256) void stats_cvt(const float* __restrict__ x) {
    size_t base = (size_t)blockIdx.x * CT;
    const float4* p = (const float4*)(x + base);
    bf* ob = g_xbf + base;
    float s = 0.f, ss = 0.f;
    for (int i = threadIdx.x; i < CT / 4; i += 256) {
        float4 v = p[i];
        s += v.x + v.y + v.z + v.w;
        ss += v.x * v.x + v.y * v.y + v.z * v.z + v.w * v.w;
        union { uint2 u; __nv_bfloat162 h[2]; } pk;
        pk.h[0] = __floats2bfloat162_rn(v.x, v.y);
        pk.h[1] = __floats2bfloat162_rn(v.z, v.w);
        *(uint2*)(ob + (size_t)i * 4) = pk.u;
    }
    __shared__ float rs[8], rss[8];
    for (int off = 16; off; off >>= 1) {
        s  += __shfl_down_sync(~0u, s, off);
        ss += __shfl_down_sync(~0u, ss, off);
    }
    int wid = threadIdx.x >> 5, lane = threadIdx.x & 31;
    if (lane == 0) { rs[wid] = s; rss[wid] = ss; }
    __syncthreads();
    if (threadIdx.x == 0) {
        float S = 0.f, SS = 0.f;
        for (int i = 0; i < 8; i++) { S += rs[i]; SS += rss[i]; }
        float mu = S / (float)CT;
        float var = SS / (float)CT - mu * mu;
        g_mu[blockIdx.x] = mu;
        g_rstd[blockIdx.x] = rsqrtf(var + EPS);
    }
}

// ---------------- K2: fold instance norm into weights ----------------
__global__ __launch_bounds__(256) void prep_weights(const float* __restrict__ in_w,
                                                    const float* __restrict__ in_b) {
    int be = blockIdx.x;
    int b = be / E3, e = be % E3;
    int d = threadIdx.x;
    float w = in_w[e * Dm + d];
    float r = g_rstd[b * Dm + d];
    float m = g_mu[b * Dm + d];
    float we = w * r;
    g_weff[(size_t)be * Dm + d] = __float2bfloat16(we);
    __shared__ float red[256];
    red[d] = we * m;
    __syncthreads();
    for (int s = 128; s > 0; s >>= 1) {
        if (d < s) red[d] += red[d + s];
        __syncthreads();
    }
    if (d == 0) g_bias[be] = in_b[e] - red[0];
}

__global__ __launch_bounds__(256) void conv_outw(const float* __restrict__ out_w) {
    int i = blockIdx.x * 256 + threadIdx.x;
    g_wout[i] = __float2bfloat16(out_w[i]);
}

// ---------------- K3: fused qkv GEMM + (q-softmax | exp/ctx-partial) ----------------
// grid (3, 512, 2). et=0: q rows 0..255. et=1: k heads0-3 + v heads0-3.
// et=2: k heads4-7 + v heads4-7. 256 threads, block tile 256x128, warp 64x64.
// smem: A[2][256][72] @0 (73728), B[2][64][136] @73728 (34816), biasT @108544 (1024),
//       S_s @109568 (512), vbuf @110080 (34816) -> 144896.
//       overlays: stage f32[128][132] @0, kbuf bf16[128][136] @73728.
#define QKV_SB    73728
#define QKV_SBIAS 108544
#define QKV_SS    109568
#define QKV_SVB   110080
#define QKV_SMEM  144896

__global__ __launch_bounds__(256) void qkv_fused() {
    extern __shared__ __align__(16) char sm[];
    bf (*A_s)[256][72] = (bf(*)[256][72])sm;
    bf (*B_s)[64][136] = (bf(*)[64][136])(sm + QKV_SB);
    float (*stage)[132] = (float(*)[132])sm;
    bf (*kbuf)[136] = (bf(*)[136])(sm + QKV_SB);
    bf (*vbuf)[136] = (bf(*)[136])(sm + QKV_SVB);
    float* biasT = (float*)(sm + QKV_SBIAS);
    float* S_s   = (float*)(sm + QKV_SS);

    const int et = blockIdx.x;   // 0 q, 1 kv(heads0-3), 2 kv(heads4-7)
    const int tt = blockIdx.y;   // 512 t-tiles
    const int b  = blockIdx.z;

    const int tid = threadIdx.x;
    const int w = tid >> 5;
    const int wm = w >> 1, wn = w & 1;     // 4x2 warps, 64x64 tiles

    auto rowmap = [&](int r) {
        return et == 0 ? r : (256 + (et - 1) * 128 + r + (r & 128));
    };
    biasT[tid] = g_bias[b * E3 + rowmap(tid)];

    const bf* Wb = g_weff + (size_t)b * E3 * Dm;
    const bf* Bptr = g_xbf + (size_t)b * Dm * CT + (size_t)tt * 128;

    wmma::fragment<wmma::accumulator, 16, 16, 16, float> acc[4][4];
    #pragma unroll
    for (int i = 0; i < 4; i++)
        #pragma unroll
        for (int j = 0; j < 4; j++) wmma::fill_fragment(acc[i][j], 0.0f);

    auto loadA = [&](int s, int k0) {
        #pragma unroll
        for (int it = 0; it < 8; it++) {
            int idx = tid + it * 256;
            int r = idx >> 3, c8 = (idx & 7) * 8;
            cp16(&A_s[s][r][c8], Wb + (size_t)rowmap(r) * Dm + k0 + c8);
        }
    };
    auto loadB = [&](int s, int k0) {
        #pragma unroll
        for (int it = 0; it < 4; it++) {
            int idx = tid + it * 256;
            int r = idx >> 4, c8 = (idx & 15) * 8;
            cp16(&B_s[s][r][c8], Bptr + (size_t)(k0 + r) * CT + c8);
        }
    };
    auto mma_chunk = [&](int st) {
        #pragma unroll
        for (int kk = 0; kk < 64; kk += 16) {
            wmma::fragment<wmma::matrix_a, 16, 16, 16, bf, wmma::row_major> af[4];
            wmma::fragment<wmma::matrix_b, 16, 16, 16, bf, wmma::row_major> bfr[4];
            #pragma unroll
            for (int i = 0; i < 4; i++)
                wmma::load_matrix_sync(af[i], &A_s[st][wm * 64 + i * 16][kk], 72);
            #pragma unroll
            for (int j = 0; j < 4; j++)
                wmma::load_matrix_sync(bfr[j], &B_s[st][kk][wn * 64 + j * 16], 136);
            #pragma unroll
            for (int i = 0; i < 4; i++)
                #pragma unroll
                for (int j = 0; j < 4; j++)
                    wmma::mma_sync(acc[i][j], af[i], bfr[j], acc[i][j]);
        }
    };

    // 2-stage pipeline, K chunks of 64 (4 chunks)
    loadA(0, 0); loadB(0, 0); CP_COMMIT();
    loadA(1, 64); loadB(1, 64); CP_COMMIT();
    CP_WAIT1(); __syncthreads();
    mma_chunk(0);
    __syncthreads();
    loadA(0, 128); loadB(0, 128); CP_COMMIT();
    CP_WAIT1(); __syncthreads();
    mma_chunk(1);
    __syncthreads();
    loadA(1, 192); loadB(1, 192); CP_COMMIT();
    CP_WAIT1(); __syncthreads();
    mma_chunk(0);
    CP_WAIT0(); __syncthreads();
    mma_chunk(1);
    __syncthreads();   // buffers dead; overlays live

    auto store_chunk = [&](int g) {
        if ((wm >> 1) == g) {
            int rbase = (wm & 1) * 64;
            #pragma unroll
            for (int i = 0; i < 4; i++)
                #pragma unroll
                for (int j = 0; j < 4; j++)
                    wmma::store_matrix_sync(&stage[rbase + i * 16][wn * 64 + j * 16],
                                            acc[i][j], 132, wmma::mem_row_major);
        }
        __syncthreads();
    };

    if (et == 0) {
        // q: per 128-row chunk: softmax over each 32-row head block, write q~
        #pragma unroll
        for (int g = 0; g < 2; g++) {
            store_chunk(g);
            {
                int col = tid & 127;
                int hb0 = (tid >> 7) * 2;   // this thread handles head blocks hb0, hb0+1
                #pragma unroll
                for (int hh = 0; hh < 2; hh++) {
                    int rbase = (hb0 + hh) * 32;
                    float vbf[32];
                    float m = -1e30f;
                    #pragma unroll
                    for (int rr = 0; rr < 32; rr++) {
                        float vv = stage[rbase + rr][col] + biasT[g * 128 + rbase + rr];
                        vbf[rr] = vv; m = fmaxf(m, vv);
                    }
                    float s = 0.f;
                    #pragma unroll
                    for (int rr = 0; rr < 32; rr++) { vbf[rr] = __expf(vbf[rr] - m); s += vbf[rr]; }
                    float inv = SCALE / s;
                    #pragma unroll
                    for (int rr = 0; rr < 32; rr++)
                        stage[rbase + rr][col] = vbf[rr] * inv;
                }
            }
            __syncthreads();
            #pragma unroll
            for (int it = 0; it < 8; it++) {
                int idx = tid + it * 256;
                int r = idx >> 4, c8 = (idx & 15) * 8;
                union { uint4 u; __nv_bfloat162 h2[4]; } o;
                #pragma unroll
                for (int u2 = 0; u2 < 4; u2++)
                    o.h2[u2] = __floats2bfloat162_rn(stage[r][c8 + 2 * u2],
                                                     stage[r][c8 + 2 * u2 + 1]);
                *(uint4*)(g_qt + (size_t)(b * Dm + g * 128 + r) * CT + (size_t)tt * 128 + c8) = o.u;
            }
            __syncthreads();
        }
    } else {
        const int hg = et - 1;
        const int c = tt >> 3, slot = tt & 7;
        const int bc = b * Cc + c;
        // chunk 0 = k rows: exp(val+bias) -> kbuf; row-sum S
        store_chunk(0);
        {
            int row = tid >> 1, half = tid & 1;
            float bsv = biasT[row];
            float ssum = 0.f;
            #pragma unroll
            for (int cc = 0; cc < 64; cc++) {
                int col = half * 64 + cc;
                float e = __expf(stage[row][col] + bsv);
                kbuf[row][col] = __float2bfloat16(e);
                ssum += e;
            }
            ssum += __shfl_xor_sync(~0u, ssum, 1);
            if (half == 0) S_s[row] = ssum;
        }
        __syncthreads();
        // chunk 1 = v rows: (val+bias)/T -> vbuf
        store_chunk(1);
        {
            int row = tid >> 1, half = tid & 1;
            float bsv = biasT[128 + row];
            #pragma unroll
            for (int cc = 0; cc < 64; cc++) {
                int col = half * 64 + cc;
                vbuf[row][col] = __float2bfloat16((stage[row][col] + bsv) * (1.0f / 1024.0f));
            }
        }
        __syncthreads();
        // ctx partial: per head hh (4), ctx[fk 32][fv 32] over 128 t
        // warp w: head w&3, t-half w>>2
        {
            int hh = w & 3, th = w >> 2;
            wmma::fragment<wmma::accumulator, 16, 16, 16, float> ca[2][2];
            #pragma unroll
            for (int i = 0; i < 2; i++)
                #pragma unroll
                for (int j = 0; j < 2; j++) wmma::fill_fragment(ca[i][j], 0.f);
            #pragma unroll
            for (int kk = 0; kk < 64; kk += 16) {
                wmma::fragment<wmma::matrix_a, 16, 16, 16, bf, wmma::row_major> af;
                wmma::fragment<wmma::matrix_b, 16, 16, 16, bf, wmma::col_major> bv;
                #pragma unroll
                for (int i = 0; i < 2; i++) {
                    wmma::load_matrix_sync(af, &kbuf[hh * 32 + i * 16][th * 64 + kk], 136);
                    #pragma unroll
                    for (int j = 0; j < 2; j++) {
                        wmma::load_matrix_sync(bv, &vbuf[hh * 32 + j * 16][th * 64 + kk], 136);
                        wmma::mma_sync(ca[i][j], af, bv, ca[i][j]);
                    }
                }
            }
            __syncthreads();
            // reduce t-halves: warps 4-7 store, warps 0-3 add, then write gmem
            float* hstage = (float*)sm + hh * 1280;   // [32][40] per head
            if (th == 1) {
                #pragma unroll
                for (int i = 0; i < 2; i++)
                    #pragma unroll
                    for (int j = 0; j < 2; j++)
                        wmma::store_matrix_sync(&hstage[(i * 16) * 40 + j * 16],
                                                ca[i][j], 40, wmma::mem_row_major);
            }
            __syncthreads();
            if (th == 0) {
                float* dst = g_ctxp + (((size_t)bc * 8 + slot) * Hh + hg * 4 + hh) * 1024;
                wmma::fragment<wmma::accumulator, 16, 16, 16, float> tmp;
                #pragma unroll
                for (int i = 0; i < 2; i++)
                    #pragma unroll
                    for (int j = 0; j < 2; j++) {
                        wmma::load_matrix_sync(tmp, &hstage[(i * 16) * 40 + j * 16],
                                               40, wmma::mem_row_major);
                        for (int e = 0; e < tmp.num_elements; e++) ca[i][j].x[e] += tmp.x[e];
                        wmma::store_matrix_sync(dst + (i * 16) * 32 + j * 16,
                                                ca[i][j], 32, wmma::mem_row_major);
                    }
            }
        }
        if (tid < 128)
            g_Sp[((size_t)bc * 8 + slot) * 256 + hg * 128 + tid] = S_s[tid];
    }
}

// ---------------- K4: Mcat = W_out x blockdiag(ctx^T/S), reducing 8 slots ----------------
__global__ __launch_bounds__(256) void mcat_kernel() {
    int bc = blockIdx.x;
    __shared__ float Ssum[256];
    __shared__ bf ctxs[8192];   // [h][fv][fk]
    int tid = threadIdx.x;
    {
        float s = 0.f;
        #pragma unroll
        for (int sl = 0; sl < 8; sl++)
            s += g_Sp[((size_t)bc * 8 + sl) * 256 + tid];
        Ssum[tid] = s;
    }
    __syncthreads();
    for (int i = tid; i < 8192; i += 256) {
        int h = i >> 10, fk = (i >> 5) & 31, fv = i & 31;
        float v = 0.f;
        #pragma unroll
        for (int sl = 0; sl < 8; sl++)
            v += g_ctxp[(((size_t)bc * 8 + sl) * Hh + h) * 1024 + fk * 32 + fv];
        ctxs[h * 1024 + fv * 32 + fk] = __float2bfloat16(v / Ssum[h * 32 + fk]);
    }
    __syncthreads();
    int e = tid;
    const bf* wrow = g_wout + e * Dm;
    #pragma unroll 1
    for (int h = 0; h < 8; h++) {
        float wv[32];
        #pragma unroll
        for (int fv = 0; fv < 32; fv++) wv[fv] = __bfloat162float(wrow[h * 32 + fv]);
        float o[32];
        #pragma unroll
        for (int fk = 0; fk < 32; fk++) o[fk] = 0.f;
        #pragma unroll
        for (int fv = 0; fv < 32; fv++) {
            float wf = wv[fv];
            const bf* cr = ctxs + h * 1024 + fv * 32;
            #pragma unroll
            for (int fk = 0; fk < 32; fk++) o[fk] += wf * __bfloat162float(cr[fk]);
        }
        __align__(16) bf ob[32];
        #pragma unroll
        for (int fk = 0; fk < 32; fk++) ob[fk] = __float2bfloat16(o[fk]);
        uint4* dst = (uint4*)(g_mcat + ((size_t)bc * Dm + e) * Dm + h * 32);
        const uint4* src = (const uint4*)ob;
        #pragma unroll
        for (int q2 = 0; q2 < 4; q2++) dst[q2] = src[q2];
    }
}

// ---------------- K5: out = Mcat[bc] @ q~ + out_b + x (4-warp 64x64 3-stage) ----------------
#define FG_SB    55296
#define FG_SBIAS 107520
#define FG_SMEM  108032

__global__ __launch_bounds__(128) void final_gemm(const float* __restrict__ x,
                                                  const float* __restrict__ out_b,
                                                  float* __restrict__ out) {
    extern __shared__ __align__(16) char sm[];
    bf (*A_s)[128][72] = (bf(*)[128][72])sm;
    bf (*B_s)[64][136] = (bf(*)[64][136])(sm + FG_SB);
    float (*stage)[132] = (float(*)[132])sm;
    float* biasO = (float*)(sm + FG_SBIAS);

    const int bx = blockIdx.x;   // t tile (8)
    const int by = blockIdx.y;   // e half (2)
    const int bc = blockIdx.z;   // 128
    const int b = bc >> 6, c = bc & 63;

    const int tid = threadIdx.x;
    const int w = tid >> 5;
    const int wm = w >> 1, wn = w & 1;

    biasO[tid] = out_b[by * 128 + tid];

    const bf* Aptr = g_mcat + (size_t)bc * Dm * Dm + (size_t)by * 128 * Dm;
    const bf* Bptr = g_qt + (size_t)b * Dm * CT + (size_t)c * Tt + (size_t)bx * 128;

    wmma::fragment<wmma::accumulator, 16, 16, 16, float> acc[4][4];
    #pragma unroll
    for (int i = 0; i < 4; i++)
        #pragma unroll
        for (int j = 0; j < 4; j++) wmma::fill_fragment(acc[i][j], 0.0f);

    auto loadA = [&](int s, int k0) {
        #pragma unroll
        for (int it = 0; it < 8; it++) {
            int idx = tid + it * 128;
            int r = idx >> 3, c8 = (idx & 7) * 8;
            cp16(&A_s[s][r][c8], Aptr + (size_t)r * Dm + k0 + c8);
        }
    };
    auto loadB = [&](int s, int k0) {
        #pragma unroll
        for (int it = 0; it < 8; it++) {
            int idx = tid + it * 128;
            int r = idx >> 4, c8 = (idx & 15) * 8;
            cp16(&B_s[s][r][c8], Bptr + (size_t)(k0 + r) * CT + c8);
        }
    };
    auto mma_chunk = [&](int st) {
        #pragma unroll
        for (int kk = 0; kk < 64; kk += 16) {
            wmma::fragment<wmma::matrix_a, 16, 16, 16, bf, wmma::row_major> af[4];
            wmma::fragment<wmma::matrix_b, 16, 16, 16, bf, wmma::row_major> bfr[4];
            #pragma unroll
            for (int i = 0; i < 4; i++)
                wmma::load_matrix_sync(af[i], &A_s[st][wm * 64 + i * 16][kk], 72);
            #pragma unroll
            for (int j = 0; j < 4; j++)
                wmma::load_matrix_sync(bfr[j], &B_s[st][kk][wn * 64 + j * 16], 136);
            #pragma unroll
            for (int i = 0; i < 4; i++)
                #pragma unroll
                for (int j = 0; j < 4; j++)
                    wmma::mma_sync(acc[i][j], af[i], bfr[j], acc[i][j]);
        }
    };

    loadA(0, 0);   loadB(0, 0);   CP_COMMIT();
    loadA(1, 64);  loadB(1, 64);  CP_COMMIT();
    CP_WAIT1(); __syncthreads();
    mma_chunk(0);
    loadA(2, 128); loadB(2, 128); CP_COMMIT();
    CP_WAIT1(); __syncthreads();
    mma_chunk(1);
    loadA(0, 192); loadB(0, 192); CP_COMMIT();
    CP_WAIT1(); __syncthreads();
    mma_chunk(2);
    CP_WAIT0(); __syncthreads();
    mma_chunk(0);
    __syncthreads();

    #pragma unroll
    for (int i = 0; i < 4; i++)
        #pragma unroll
        for (int j = 0; j < 4; j++)
            wmma::store_matrix_sync(&stage[wm * 64 + i * 16][wn * 64 + j * 16],
                                    acc[i][j], 132, wmma::mem_row_major);
    __syncthreads();

    #pragma unroll
    for (int it = 0; it < 32; it++) {
        int idx = tid + it * 128;
        int r = idx >> 5, c4 = (idx & 31) * 4;
        int e = by * 128 + r;
        size_t gi = ((size_t)(b * Dm + e) * Cc + c) * Tt + (size_t)bx * 128 + c4;
        float4 xv = *(const float4*)(x + gi);
        float bo = biasO[r];
        float4 o;
        o.x = stage[r][c4 + 0] + bo + xv.x;
        o.y = stage[r][c4 + 1] + bo + xv.y;
        o.z = stage[r][c4 + 2] + bo + xv.z;
        o.w = stage[r][c4 + 3] + bo + xv.w;
        *(float4*)(out + gi) = o;
    }
}

// ---------------- launch ----------------
extern "C" void kernel_launch(void* const* d_in, const int* in_sizes, int n_in,
                              void* d_out, int out_size) {
    const float* x     = (const float*)d_in[0];
    const float* in_w  = (const float*)d_in[1];
    const float* in_b  = (const float*)d_in[2];
    const float* out_w = (const float*)d_in[3];
    const float* out_b = (const float*)d_in[4];
    float* out = (float*)d_out;

    cudaFuncSetAttribute(qkv_fused, cudaFuncAttributeMaxDynamicSharedMemorySize, QKV_SMEM);
    cudaFuncSetAttribute(final_gemm, cudaFuncAttributeMaxDynamicSharedMemorySize, FG_SMEM);

    stats_cvt<<<Bn * Dm, 256>>>(x);
    prep_weights<<<Bn * E3, 256>>>(in_w, in_b);
    conv_outw<<<Dm * Dm / 256, 256>>>(out_w);
    qkv_fused<<<dim3(3, CT / 128, Bn), 256, QKV_SMEM>>>();
    mcat_kernel<<<Bn * Cc, 256>>>();
    final_gemm<<<dim3(Tt / 128, 2, Bn * Cc), 128, FG_SMEM>>>(x, out_b, out);
}